// round 4
// baseline (speedup 1.0000x reference)
#include <cuda_runtime.h>
#include <math.h>
#include <stdint.h>
#include <stddef.h>

#define NRAYS 2048
#define NSAMP 128
#define NS (NRAYS * NSAMP)   // 262144 samples per pass

// ---------------- static scratch (no allocations allowed) ----------------
__device__ float g_enc[NS * 96];        // IPE encodings
__device__ float g_x0[NS * 256];        // activation ping
__device__ float g_x1[NS * 256];        // activation pong
__device__ float g_h [NS * 128];        // post-Wd hidden
__device__ float g_rf[NS * 6];          // raw heads
__device__ float g_direnc[NRAYS * 27];
__device__ float g_raynorm[NRAYS];
__device__ float g_raybias[NRAYS * 128];
__device__ float g_weights[NS];
__device__ float g_mus[NS];
__device__ float g_smsig[NS];
__device__ float g_lt[NS];
__device__ float g_pib[NS];
__device__ float g_tfine[NRAYS * 129];

// ---------------- helpers ----------------
__device__ __forceinline__ float sigmoidf_(float x) {
    return 1.0f / (1.0f + expf(-x));
}
__device__ __forceinline__ float acdf_(float x) {
    float x3 = x * x * x;
    return 0.5f * (1.0f + tanhf(0.7978845608028654f * (x + 0.044715f * x3)));
}
__device__ __forceinline__ uint32_t f2tf32(float x) {
    uint32_t r;
    asm("cvt.rna.tf32.f32 %0, %1;" : "=r"(r) : "f"(x));
    return r;
}
// split a float into tf32 hi + tf32 lo
__device__ __forceinline__ void tf32split(float x, uint32_t& h, uint32_t& l) {
    h = f2tf32(x);
    l = f2tf32(x - __uint_as_float(h));
}

__device__ __forceinline__ void cp16(void* s, const void* g) {
    uint32_t sa = (uint32_t)__cvta_generic_to_shared(s);
    asm volatile("cp.async.ca.shared.global [%0], [%1], 16;" :: "r"(sa), "l"(g));
}
__device__ __forceinline__ void cp_commit() {
    asm volatile("cp.async.commit_group;" ::: "memory");
}
__device__ __forceinline__ void cp_wait0() {
    asm volatile("cp.async.wait_group 0;" ::: "memory");
}

#define MMA_TF32(d, a0, a1, a2, a3, b0, b1)                                  \
    asm volatile(                                                            \
        "mma.sync.aligned.m16n8k8.row.col.f32.tf32.tf32.f32 "                \
        "{%0,%1,%2,%3}, {%4,%5,%6,%7}, {%8,%9}, {%0,%1,%2,%3};"              \
        : "+f"(d[0]), "+f"(d[1]), "+f"(d[2]), "+f"(d[3])                     \
        : "r"(a0), "r"(a1), "r"(a2), "r"(a3), "r"(b0), "r"(b1))

// ---------------- ray setup: viewdirs + dir encoding + |rd| ----------------
__global__ void ray_setup_kernel(const float* __restrict__ rd) {
    int r = blockIdx.x * blockDim.x + threadIdx.x;
    if (r >= NRAYS) return;
    float x = rd[r * 3 + 0], y = rd[r * 3 + 1], z = rd[r * 3 + 2];
    float n = sqrtf(x * x + y * y + z * z);
    g_raynorm[r] = n;
    float inv = 1.0f / n;
    float v[3] = {x * inv, y * inv, z * inv};
    float* de = g_direnc + r * 27;
    de[0] = v[0]; de[1] = v[1]; de[2] = v[2];
#pragma unroll
    for (int f = 0; f < 4; f++) {
        float fr = (float)(1 << f);
#pragma unroll
        for (int k = 0; k < 3; k++) {
            float xx = v[k] * fr;
            de[3 + f * 3 + k]  = sinf(xx);
            de[15 + f * 3 + k] = cosf(xx);
        }
    }
}

// per-ray bias for the Wd layer: bd[o] + sum_j direnc[j] * Wd[256+j][o]
__global__ void ray_bias_kernel(const float* __restrict__ Wd, const float* __restrict__ bd) {
    int r = blockIdx.x;
    int o = threadIdx.x;   // 0..127
    __shared__ float de[27];
    if (o < 27) de[o] = g_direnc[r * 27 + o];
    __syncthreads();
    float a = bd[o];
#pragma unroll
    for (int j = 0; j < 27; j++) a += de[j] * Wd[(256 + j) * 128 + o];
    g_raybias[r * 128 + o] = a;
}

// ---------------- cast_rays + integrated positional encoding ----------------
__global__ void ipe_kernel(const float* __restrict__ ro, const float* __restrict__ rd,
                           const float* __restrict__ rr, const float* __restrict__ tsrc) {
    int s = blockIdx.x * blockDim.x + threadIdx.x;
    if (s >= NS) return;
    int ray = s >> 7, i = s & 127;
    float t0, t1;
    if (tsrc) {
        t0 = tsrc[ray * 129 + i];
        t1 = tsrc[ray * 129 + i + 1];
    } else {
        t0 = 2.0f + 4.0f * ((float)i / 128.0f);
        t1 = 2.0f + 4.0f * ((float)(i + 1) / 128.0f);
    }
    float c  = 0.5f * (t0 + t1);
    float dd = 0.5f * (t1 - t0);
    float d2s = dd * dd;
    float d4  = d2s * d2s;
    float c2  = c * c;
    float denom = 3.0f * c2 + d2s;
    float t_mean = c + 2.0f * c * d2s / denom;
    float t_var  = d2s * (1.0f / 3.0f) - (4.0f / 15.0f) * (d4 * (12.0f * c2 - d2s)) / (denom * denom);
    float rrv = rr[ray];
    float r_var = rrv * rrv * (c2 * 0.25f + (5.0f / 12.0f) * d2s - (4.0f / 15.0f) * d4 / denom);

    float rdv[3] = {rd[ray * 3 + 0], rd[ray * 3 + 1], rd[ray * 3 + 2]};
    float rov[3] = {ro[ray * 3 + 0], ro[ray * 3 + 1], ro[ray * 3 + 2]};
    float dn2 = rdv[0] * rdv[0] + rdv[1] * rdv[1] + rdv[2] * rdv[2];
    float invd2 = 1.0f / fmaxf(dn2, 1e-10f);
    float mean[3], cov[3];
#pragma unroll
    for (int k = 0; k < 3; k++) {
        mean[k] = rov[k] + rdv[k] * t_mean;
        float dok = rdv[k] * rdv[k];
        cov[k] = t_var * dok + r_var * (1.0f - dok * invd2);
    }

    float* e = g_enc + (size_t)s * 96;
    float scale = 1.0f;
#pragma unroll 4
    for (int deg = 0; deg < 16; deg++) {
        float sc2 = scale * scale;
#pragma unroll
        for (int k = 0; k < 3; k++) {
            int idx = deg * 3 + k;
            float yv = cov[k] * sc2;
            if (yv > 60.0f) {
                e[idx] = 0.0f;
                e[48 + idx] = 0.0f;
            } else {
                float att = expf(-0.5f * yv);
                float y = mean[k] * scale;
                double kd = rint((double)y * 0.15915494309189535);
                float rp = (float)((double)y - kd * 6.283185307179586);
                float sy, cy;
                sincosf(rp, &sy, &cy);
                e[idx]      = sy * att;
                e[48 + idx] = cy * att;
            }
        }
        scale *= 2.0f;
    }
}

// ---------------- tf32x3 tensor-core GEMM, raw-fp32 smem + cp.async ----------------
// C[M,N] = act(A[M,K] @ W[K,N] + bias).
// BM=BN=128, BK=8, 256 threads, 8 warps 4(m)x2(n), warp tile 32x64.
// smem holds RAW fp32; hi/lo tf32 split happens at fragment-load time.
template<bool RELU, bool RAYBIAS>
__global__ void __launch_bounds__(256, 2) sgemm_tc(
    const float* __restrict__ A, const float* __restrict__ W,
    const float* __restrict__ bias, float* __restrict__ C,
    int K, int N)
{
    // A: [m][k] rows of 8 floats padded to 12 (48B, 16B-aligned, conflict-free:
    //    bank = 12*g + t4 distinct for g<8,t4<8)
    // B: [k][n] rows of 128 floats padded to 136 (bank = 8*t4 + g distinct)
    __shared__ float As[2][128][12];
    __shared__ float Bs[2][8][136];

    const int tid  = threadIdx.x;
    const int bm   = blockIdx.x * 128;
    const int bn   = blockIdx.y * 128;
    const int wid  = tid >> 5;
    const int lane = tid & 31;
    const int wm   = (wid & 3) * 32;
    const int wn   = (wid >> 2) * 64;
    const int g    = lane >> 2;
    const int t4   = lane & 3;

    // cp.async mappings: A tile 128x8 (2 chunks of 16B per row), B tile 8x128 (32 chunks/row)
    const int arow = tid >> 1, achk = (tid & 1) * 4;
    const int brow = tid >> 5, bchk = (tid & 31) * 4;
    const float* Ap = A + (size_t)(bm + arow) * K + achk;
    const float* Wp = W + (size_t)brow * N + bn + bchk;

    float d[2][8][4];
#pragma unroll
    for (int mt = 0; mt < 2; mt++)
#pragma unroll
        for (int nt = 0; nt < 8; nt++)
#pragma unroll
            for (int q = 0; q < 4; q++) d[mt][nt][q] = 0.0f;

    const int nStage = K >> 3;

    // prologue: stage 0
    cp16(&As[0][arow][achk], Ap);
    cp16(&Bs[0][brow][bchk], Wp);
    cp_commit();

    for (int s = 0; s < nStage; ++s) {
        const int buf = s & 1;
        cp_wait0();
        __syncthreads();

        if (s + 1 < nStage) {
            cp16(&As[buf ^ 1][arow][achk], Ap + (s + 1) * 8);
            cp16(&Bs[buf ^ 1][brow][bchk], Wp + (size_t)(s + 1) * 8 * N);
            cp_commit();
        }

        // A fragments: split raw floats into tf32 hi/lo
        uint32_t aH[2][4], aL[2][4];
#pragma unroll
        for (int mt = 0; mt < 2; mt++) {
            int m0 = wm + mt * 16;
            float x0 = As[buf][m0 + g][t4];
            float x1 = As[buf][m0 + 8 + g][t4];
            float x2 = As[buf][m0 + g][t4 + 4];
            float x3 = As[buf][m0 + 8 + g][t4 + 4];
            tf32split(x0, aH[mt][0], aL[mt][0]);
            tf32split(x1, aH[mt][1], aL[mt][1]);
            tf32split(x2, aH[mt][2], aL[mt][2]);
            tf32split(x3, aH[mt][3], aL[mt][3]);
        }

#pragma unroll
        for (int nt = 0; nt < 8; nt++) {
            int n0 = wn + nt * 8;
            float y0 = Bs[buf][t4][n0 + g];
            float y1 = Bs[buf][t4 + 4][n0 + g];
            uint32_t bH0, bL0, bH1, bL1;
            tf32split(y0, bH0, bL0);
            tf32split(y1, bH1, bL1);
#pragma unroll
            for (int mt = 0; mt < 2; mt++) {
                MMA_TF32(d[mt][nt], aH[mt][0], aH[mt][1], aH[mt][2], aH[mt][3], bH0, bH1);
                MMA_TF32(d[mt][nt], aL[mt][0], aL[mt][1], aL[mt][2], aL[mt][3], bH0, bH1);
                MMA_TF32(d[mt][nt], aH[mt][0], aH[mt][1], aH[mt][2], aH[mt][3], bL0, bL1);
            }
        }
        __syncthreads();
    }

    // epilogue
    const int rayb = RAYBIAS ? (bm >> 7) * 128 : 0;
#pragma unroll
    for (int mt = 0; mt < 2; mt++) {
#pragma unroll
        for (int nt = 0; nt < 8; nt++) {
            int r0 = bm + wm + mt * 16 + g;
            int c0 = bn + wn + nt * 8 + 2 * t4;
            float b0v = RAYBIAS ? bias[rayb + c0]     : bias[c0];
            float b1v = RAYBIAS ? bias[rayb + c0 + 1] : bias[c0 + 1];
            float v00 = d[mt][nt][0] + b0v;
            float v01 = d[mt][nt][1] + b1v;
            float v10 = d[mt][nt][2] + b0v;
            float v11 = d[mt][nt][3] + b1v;
            if (RELU) {
                v00 = fmaxf(v00, 0.0f); v01 = fmaxf(v01, 0.0f);
                v10 = fmaxf(v10, 0.0f); v11 = fmaxf(v11, 0.0f);
            }
            float2 lo = make_float2(v00, v01);
            float2 hi = make_float2(v10, v11);
            *(float2*)&C[(size_t)r0 * N + c0]       = lo;
            *(float2*)&C[(size_t)(r0 + 8) * N + c0] = hi;
        }
    }
}

// ---------------- thin heads: sigma(256->1), [mu,sig](256->2), rgb(128->3) ----------------
__global__ void __launch_bounds__(256) heads_kernel(
    const float* __restrict__ X3, const float* __restrict__ H,
    const float* __restrict__ Ws, const float* __restrict__ bs,
    const float* __restrict__ Wm, const float* __restrict__ bm,
    const float* __restrict__ Wr, const float* __restrict__ br,
    float* __restrict__ RF)
{
    int gw = (blockIdx.x * 256 + threadIdx.x) >> 5;
    int lane = threadIdx.x & 31;
    if (gw >= NS) return;
    const bool hasM = (Wm != nullptr);
    const float* x = X3 + (size_t)gw * 256;
    float s0 = 0.0f, s1 = 0.0f, s2 = 0.0f;
#pragma unroll
    for (int i = 0; i < 8; i++) {
        int c = lane + 32 * i;
        float xv = x[c];
        s0 += xv * Ws[c];
        if (hasM) {
            s1 += xv * Wm[2 * c];
            s2 += xv * Wm[2 * c + 1];
        }
    }
    const float* h = H + (size_t)gw * 128;
    float r = 0.0f, g = 0.0f, b = 0.0f;
#pragma unroll
    for (int i = 0; i < 4; i++) {
        int c = lane + 32 * i;
        float hv = h[c];
        r += hv * Wr[3 * c];
        g += hv * Wr[3 * c + 1];
        b += hv * Wr[3 * c + 2];
    }
#pragma unroll
    for (int o = 16; o > 0; o >>= 1) {
        s0 += __shfl_down_sync(0xffffffffu, s0, o);
        s1 += __shfl_down_sync(0xffffffffu, s1, o);
        s2 += __shfl_down_sync(0xffffffffu, s2, o);
        r  += __shfl_down_sync(0xffffffffu, r, o);
        g  += __shfl_down_sync(0xffffffffu, g, o);
        b  += __shfl_down_sync(0xffffffffu, b, o);
    }
    if (lane == 0) {
        float* f = RF + (size_t)gw * 6;
        f[0] = r + br[0];
        f[1] = g + br[1];
        f[2] = b + br[2];
        f[3] = s0 + bs[0];
        if (hasM) {
            f[4] = s1 + bm[0];
            f[5] = s2 + bm[1];
        }
    }
}

// ---------------- coarse volume render + PDF ingredients ----------------
__global__ void vrender_coarse_kernel(float* __restrict__ out) {
    int r = blockIdx.x * blockDim.x + threadIdx.x;
    if (r >= NRAYS) return;
    float nrm = g_raynorm[r];
    float T = 1.0f, cr = 0.0f, cg = 0.0f, cb = 0.0f;
    for (int i = 0; i < 128; i++) {
        const float* f = g_rf + (size_t)(r * 128 + i) * 6;
        float t0 = 2.0f + 4.0f * ((float)i / 128.0f);
        float t1 = 2.0f + 4.0f * ((float)(i + 1) / 128.0f);
        float sr = sigmoidf_(f[0]);
        float sg = sigmoidf_(f[1]);
        float sb = sigmoidf_(f[2]);
        float sigma = fmaxf(f[3], 0.0f);
        float alpha = 1.0f - expf(-sigma * (t1 - t0) * nrm);
        float w = alpha * T;
        T *= (1.0f - alpha + 1e-10f);
        cr += w * sr; cg += w * sg; cb += w * sb;
        int si = r * 128 + i;
        g_weights[si] = w;
        float mu = sigmoidf_(f[4]);
        float ss = (sigmoidf_(f[5]) + 0.001f) * 2.0f;
        g_mus[si] = mu;
        g_smsig[si] = ss;
        float l = acdf_((0.0f - mu) / ss);
        g_lt[si] = l;
        g_pib[si] = acdf_((1.0f - mu) / ss) - l;
    }
    out[r * 3 + 0] = cr;
    out[r * 3 + 1] = cg;
    out[r * 3 + 2] = cb;
}

// ---------------- inverse-CDF fine sampling ----------------
__global__ void sample_pdf_kernel() {
    int r = blockIdx.x * blockDim.x + threadIdx.x;
    if (r >= NRAYS) return;
    float wl[128];
    float cdf[129];
    float sum = 0.0f;
    for (int i = 0; i < 128; i++) {
        float w = g_weights[r * 128 + i] + 1e-5f;
        wl[i] = w;
        sum += w;
    }
    float inv = 1.0f / sum;
    cdf[0] = 0.0f;
    float run = 0.0f;
    for (int i = 0; i < 128; i++) {
        run += wl[i] * inv;
        cdf[i + 1] = run;
    }
    int idx = 0;
    const float step = (1.0f - 1e-5f) / 128.0f;
    for (int i = 0; i < 129; i++) {
        float u = step * (float)i;
        while (idx < 127 && cdf[idx + 1] <= u) idx++;
        float pdfv = wl[idx] * inv;
        float frac = (u - cdf[idx]) / fmaxf(pdfv, 1e-10f);
        frac = fminf(fmaxf(frac, 0.0f), 1.0f);
        int si = r * 128 + idx;
        float p = g_lt[si] + frac * g_pib[si];
        p = fminf(fmaxf(p, 1e-5f), 1.0f - 1e-5f);
        float x = g_mus[si] + g_smsig[si] * 1.4142135623730951f * erfinvf(2.0f * p - 1.0f);
        x = fminf(fmaxf(x, 0.0f), 1.0f);
        float b0 = 2.0f + 4.0f * ((float)idx / 128.0f);
        float b1 = 2.0f + 4.0f * ((float)(idx + 1) / 128.0f);
        g_tfine[r * 129 + i] = b0 + x * (b1 - b0);
    }
}

// ---------------- fine volume render: rgb_f, depth_f, acc_f ----------------
__global__ void vrender_fine_kernel(float* __restrict__ out) {
    int r = blockIdx.x * blockDim.x + threadIdx.x;
    if (r >= NRAYS) return;
    float nrm = g_raynorm[r];
    float T = 1.0f, cr = 0.0f, cg = 0.0f, cb = 0.0f, dep = 0.0f, acc = 0.0f;
    for (int i = 0; i < 128; i++) {
        const float* f = g_rf + (size_t)(r * 128 + i) * 6;
        float t0 = g_tfine[r * 129 + i];
        float t1 = g_tfine[r * 129 + i + 1];
        float sr = sigmoidf_(f[0]);
        float sg = sigmoidf_(f[1]);
        float sb = sigmoidf_(f[2]);
        float sigma = fmaxf(f[3], 0.0f);
        float alpha = 1.0f - expf(-sigma * (t1 - t0) * nrm);
        float w = alpha * T;
        T *= (1.0f - alpha + 1e-10f);
        cr += w * sr; cg += w * sg; cb += w * sb;
        dep += w * 0.5f * (t0 + t1);
        acc += w;
    }
    out[6144 + r * 3 + 0] = cr;
    out[6144 + r * 3 + 1] = cg;
    out[6144 + r * 3 + 2] = cb;
    out[12288 + r] = dep;
    out[14336 + r] = acc;
}

// ---------------- host orchestration ----------------
extern "C" void kernel_launch(void* const* d_in, const int* in_sizes, int n_in,
                              void* d_out, int out_size)
{
    (void)out_size;
    const float* ro = (const float*)d_in[0];
    const float* rd = (const float*)d_in[1];
    const float* rr = (const float*)d_in[2];

    bool sigOrder = (n_in > 15 && in_sizes[15] == 512);
    int fb = sigOrder ? 17 : 15;
    int mb = sigOrder ? 15 : 27;

    const float* cW0 = (const float*)d_in[3];
    const float* cb0 = (const float*)d_in[4];
    const float* cWh = (const float*)d_in[5];
    const float* cbh = (const float*)d_in[6];
    const float* cWs = (const float*)d_in[7];
    const float* cbs = (const float*)d_in[8];
    const float* cWb = (const float*)d_in[9];
    const float* cbb = (const float*)d_in[10];
    const float* cWd = (const float*)d_in[11];
    const float* cbd = (const float*)d_in[12];
    const float* cWr = (const float*)d_in[13];
    const float* cbr = (const float*)d_in[14];
    const float* cWm = (const float*)d_in[mb];
    const float* cbm = (const float*)d_in[mb + 1];
    const float* fW0 = (const float*)d_in[fb + 0];
    const float* fb0 = (const float*)d_in[fb + 1];
    const float* fWh = (const float*)d_in[fb + 2];
    const float* fbh = (const float*)d_in[fb + 3];
    const float* fWs = (const float*)d_in[fb + 4];
    const float* fbs = (const float*)d_in[fb + 5];
    const float* fWb = (const float*)d_in[fb + 6];
    const float* fbb = (const float*)d_in[fb + 7];
    const float* fWd = (const float*)d_in[fb + 8];
    const float* fbd = (const float*)d_in[fb + 9];
    const float* fWr = (const float*)d_in[fb + 10];
    const float* fbr = (const float*)d_in[fb + 11];

    float *p_enc, *p_x0, *p_x1, *p_h, *p_rf, *p_raybias, *p_tfine;
    cudaGetSymbolAddress((void**)&p_enc, g_enc);
    cudaGetSymbolAddress((void**)&p_x0, g_x0);
    cudaGetSymbolAddress((void**)&p_x1, g_x1);
    cudaGetSymbolAddress((void**)&p_h, g_h);
    cudaGetSymbolAddress((void**)&p_rf, g_rf);
    cudaGetSymbolAddress((void**)&p_raybias, g_raybias);
    cudaGetSymbolAddress((void**)&p_tfine, g_tfine);

    float* out = (float*)d_out;
    const dim3 gWide(NS / 128, 2);   // N=256 layers
    const dim3 gNarrow(NS / 128, 1); // N=128 layer

    ray_setup_kernel<<<(NRAYS + 127) / 128, 128>>>(rd);

    // ================= coarse pass =================
    ipe_kernel<<<NS / 128, 128>>>(ro, rd, rr, nullptr);
    ray_bias_kernel<<<NRAYS, 128>>>(cWd, cbd);
    sgemm_tc<true, false><<<gWide, 256>>>(p_enc, cW0, cb0, p_x0, 96, 256);
    sgemm_tc<true, false><<<gWide, 256>>>(p_x0, cWh,          cbh,       p_x1, 256, 256);
    sgemm_tc<true, false><<<gWide, 256>>>(p_x1, cWh + 65536,  cbh + 256, p_x0, 256, 256);
    sgemm_tc<true, false><<<gWide, 256>>>(p_x0, cWh + 131072, cbh + 512, p_x1, 256, 256);
    sgemm_tc<false, false><<<gWide, 256>>>(p_x1, cWb, cbb, p_x0, 256, 256);
    sgemm_tc<true, true><<<gNarrow, 256>>>(p_x0, cWd, p_raybias, p_h, 256, 128);
    heads_kernel<<<NS / 8, 256>>>(p_x1, p_h, cWs, cbs, cWm, cbm, cWr, cbr, p_rf);
    vrender_coarse_kernel<<<(NRAYS + 127) / 128, 128>>>(out);
    sample_pdf_kernel<<<(NRAYS + 127) / 128, 128>>>();

    // ================= fine pass =================
    ipe_kernel<<<NS / 128, 128>>>(ro, rd, rr, p_tfine);
    ray_bias_kernel<<<NRAYS, 128>>>(fWd, fbd);
    sgemm_tc<true, false><<<gWide, 256>>>(p_enc, fW0, fb0, p_x0, 96, 256);
    sgemm_tc<true, false><<<gWide, 256>>>(p_x0, fWh,          fbh,       p_x1, 256, 256);
    sgemm_tc<true, false><<<gWide, 256>>>(p_x1, fWh + 65536,  fbh + 256, p_x0, 256, 256);
    sgemm_tc<true, false><<<gWide, 256>>>(p_x0, fWh + 131072, fbh + 512, p_x1, 256, 256);
    sgemm_tc<false, false><<<gWide, 256>>>(p_x1, fWb, fbb, p_x0, 256, 256);
    sgemm_tc<true, true><<<gNarrow, 256>>>(p_x0, fWd, p_raybias, p_h, 256, 128);
    heads_kernel<<<NS / 8, 256>>>(p_x1, p_h, fWs, fbs, nullptr, nullptr, fWr, fbr, p_rf);
    vrender_fine_kernel<<<(NRAYS + 127) / 128, 128>>>(out);
}

// round 5
// speedup vs baseline: 1.5034x; 1.5034x over previous
#include <cuda_runtime.h>
#include <math.h>
#include <stdint.h>
#include <stddef.h>

#define NRAYS 2048
#define NSAMP 128
#define NS (NRAYS * NSAMP)   // 262144 samples per pass

// ---------------- static scratch (no allocations allowed) ----------------
__device__ float g_enc[NS * 96];        // IPE encodings
__device__ float g_x0[NS * 256];        // activation ping
__device__ float g_x1[NS * 256];        // activation pong
__device__ float g_h [NS * 128];        // post-Wd hidden
__device__ float g_rf[NS * 6];          // raw heads
__device__ float g_direnc[NRAYS * 27];
__device__ float g_raynorm[NRAYS];
__device__ float g_raybias[NRAYS * 128];
__device__ float g_weights[NS];
__device__ float g_mus[NS];
__device__ float g_smsig[NS];
__device__ float g_lt[NS];
__device__ float g_pib[NS];
__device__ float g_tfine[NRAYS * 129];
__device__ float g_cdf[NRAYS * 129];    // normalized CDF per ray
__device__ float g_pdfn[NS];            // normalized PDF per ray-sample

// ---------------- helpers ----------------
__device__ __forceinline__ float fast_sigmoid(float x) {
    return 1.0f / (1.0f + __expf(-x));
}
__device__ __forceinline__ float acdf_(float x) {
    // 0.5*(1+tanh(q*(x+0.044715 x^3))); tanh(z) = 2*sigmoid(2z)-1
    float x3 = x * x * x;
    float z = 0.7978845608028654f * (x + 0.044715f * x3);
    return 1.0f / (1.0f + __expf(-2.0f * z));
}
__device__ __forceinline__ uint32_t f2tf32(float x) {
    uint32_t r;
    asm("cvt.rna.tf32.f32 %0, %1;" : "=r"(r) : "f"(x));
    return r;
}

#define MMA_TF32(d, a0, a1, a2, a3, b0, b1)                                  \
    asm volatile(                                                            \
        "mma.sync.aligned.m16n8k8.row.col.f32.tf32.tf32.f32 "                \
        "{%0,%1,%2,%3}, {%4,%5,%6,%7}, {%8,%9}, {%0,%1,%2,%3};"              \
        : "+f"(d[0]), "+f"(d[1]), "+f"(d[2]), "+f"(d[3])                     \
        : "r"(a0), "r"(a1), "r"(a2), "r"(a3), "r"(b0), "r"(b1))

// ---------------- ray setup: viewdirs + dir encoding + |rd| ----------------
__global__ void ray_setup_kernel(const float* __restrict__ rd) {
    int r = blockIdx.x * blockDim.x + threadIdx.x;
    if (r >= NRAYS) return;
    float x = rd[r * 3 + 0], y = rd[r * 3 + 1], z = rd[r * 3 + 2];
    float n = sqrtf(x * x + y * y + z * z);
    g_raynorm[r] = n;
    float inv = 1.0f / n;
    float v[3] = {x * inv, y * inv, z * inv};
    float* de = g_direnc + r * 27;
    de[0] = v[0]; de[1] = v[1]; de[2] = v[2];
#pragma unroll
    for (int f = 0; f < 4; f++) {
        float fr = (float)(1 << f);
#pragma unroll
        for (int k = 0; k < 3; k++) {
            float xx = v[k] * fr;
            de[3 + f * 3 + k]  = sinf(xx);
            de[15 + f * 3 + k] = cosf(xx);
        }
    }
}

// per-ray bias for the Wd layer: bd[o] + sum_j direnc[j] * Wd[256+j][o]
__global__ void ray_bias_kernel(const float* __restrict__ Wd, const float* __restrict__ bd) {
    int r = blockIdx.x;
    int o = threadIdx.x;   // 0..127
    __shared__ float de[27];
    if (o < 27) de[o] = g_direnc[r * 27 + o];
    __syncthreads();
    float a = bd[o];
#pragma unroll
    for (int j = 0; j < 27; j++) a += de[j] * Wd[(256 + j) * 128 + o];
    g_raybias[r * 128 + o] = a;
}

// ---------------- cast_rays + integrated positional encoding ----------------
__global__ void ipe_kernel(const float* __restrict__ ro, const float* __restrict__ rd,
                           const float* __restrict__ rr, const float* __restrict__ tsrc) {
    int s = blockIdx.x * blockDim.x + threadIdx.x;
    if (s >= NS) return;
    int ray = s >> 7, i = s & 127;
    float t0, t1;
    if (tsrc) {
        t0 = tsrc[ray * 129 + i];
        t1 = tsrc[ray * 129 + i + 1];
    } else {
        t0 = 2.0f + 4.0f * ((float)i / 128.0f);
        t1 = 2.0f + 4.0f * ((float)(i + 1) / 128.0f);
    }
    float c  = 0.5f * (t0 + t1);
    float dd = 0.5f * (t1 - t0);
    float d2s = dd * dd;
    float d4  = d2s * d2s;
    float c2  = c * c;
    float denom = 3.0f * c2 + d2s;
    float t_mean = c + 2.0f * c * d2s / denom;
    float t_var  = d2s * (1.0f / 3.0f) - (4.0f / 15.0f) * (d4 * (12.0f * c2 - d2s)) / (denom * denom);
    float rrv = rr[ray];
    float r_var = rrv * rrv * (c2 * 0.25f + (5.0f / 12.0f) * d2s - (4.0f / 15.0f) * d4 / denom);

    float rdv[3] = {rd[ray * 3 + 0], rd[ray * 3 + 1], rd[ray * 3 + 2]};
    float rov[3] = {ro[ray * 3 + 0], ro[ray * 3 + 1], ro[ray * 3 + 2]};
    float dn2 = rdv[0] * rdv[0] + rdv[1] * rdv[1] + rdv[2] * rdv[2];
    float invd2 = 1.0f / fmaxf(dn2, 1e-10f);
    float mean[3], cov[3];
#pragma unroll
    for (int k = 0; k < 3; k++) {
        mean[k] = rov[k] + rdv[k] * t_mean;
        float dok = rdv[k] * rdv[k];
        cov[k] = t_var * dok + r_var * (1.0f - dok * invd2);
    }

    float* e = g_enc + (size_t)s * 96;
    float scale = 1.0f;
#pragma unroll 4
    for (int deg = 0; deg < 16; deg++) {
        float sc2 = scale * scale;
#pragma unroll
        for (int k = 0; k < 3; k++) {
            int idx = deg * 3 + k;
            float yv = cov[k] * sc2;
            if (yv > 60.0f) {
                e[idx] = 0.0f;
                e[48 + idx] = 0.0f;
            } else {
                float att = __expf(-0.5f * yv);
                float y = mean[k] * scale;
                // accurate range reduction in double, then MUFU sin/cos
                double kd = rint((double)y * 0.15915494309189535);
                float rp = (float)((double)y - kd * 6.283185307179586);
                float sy = __sinf(rp);
                float cy = __cosf(rp);
                e[idx]      = sy * att;
                e[48 + idx] = cy * att;
            }
        }
        scale *= 2.0f;
    }
}

// ---------------- tf32x3 tensor-core GEMM (R3 version: hi/lo stored in smem) ----------------
template<bool RELU, bool RAYBIAS>
__global__ void __launch_bounds__(256, 2) sgemm_tc(
    const float* __restrict__ A, const float* __restrict__ W,
    const float* __restrict__ bias, float* __restrict__ C,
    int K, int N)
{
    __shared__ uint32_t AsH[2][8][136];
    __shared__ uint32_t AsL[2][8][136];
    __shared__ uint32_t BsH[2][8][136];
    __shared__ uint32_t BsL[2][8][136];

    const int tid  = threadIdx.x;
    const int bm   = blockIdx.x * 128;
    const int bn   = blockIdx.y * 128;
    const int wid  = tid >> 5;
    const int lane = tid & 31;
    const int wm   = (wid & 3) * 32;
    const int wn   = (wid >> 2) * 64;
    const int g    = lane >> 2;
    const int t4   = lane & 3;

    const int ar = tid >> 1;
    const int ac = (tid & 1) * 4;
    const int br = tid >> 5;
    const int bc = (tid & 31) * 4;

    const float* Ap = A + (size_t)(bm + ar) * K + ac;
    const float* Wp = W + (size_t)br * N + bn + bc;

    float d[2][8][4];
#pragma unroll
    for (int mt = 0; mt < 2; mt++)
#pragma unroll
        for (int nt = 0; nt < 8; nt++)
#pragma unroll
            for (int q = 0; q < 4; q++) d[mt][nt][q] = 0.0f;

    const int nStage = K >> 3;

    float4 av = *(const float4*)Ap;
    float4 wv = *(const float4*)Wp;

    {
        float aa[4] = {av.x, av.y, av.z, av.w};
        float ww[4] = {wv.x, wv.y, wv.z, wv.w};
#pragma unroll
        for (int j = 0; j < 4; j++) {
            uint32_t h = f2tf32(aa[j]);
            AsH[0][ac + j][ar] = h;
            AsL[0][ac + j][ar] = f2tf32(aa[j] - __uint_as_float(h));
            uint32_t hw = f2tf32(ww[j]);
            BsH[0][br][bc + j] = hw;
            BsL[0][br][bc + j] = f2tf32(ww[j] - __uint_as_float(hw));
        }
    }
    __syncthreads();

    for (int s = 0; s < nStage; ++s) {
        const int buf = s & 1;
        if (s + 1 < nStage) {
            Ap += 8;
            Wp += (size_t)8 * N;
            av = *(const float4*)Ap;
            wv = *(const float4*)Wp;
        }

        uint32_t aH[2][4], aL[2][4];
#pragma unroll
        for (int mt = 0; mt < 2; mt++) {
            int m0 = wm + mt * 16;
            aH[mt][0] = AsH[buf][t4    ][m0 + g];
            aH[mt][1] = AsH[buf][t4    ][m0 + 8 + g];
            aH[mt][2] = AsH[buf][t4 + 4][m0 + g];
            aH[mt][3] = AsH[buf][t4 + 4][m0 + 8 + g];
            aL[mt][0] = AsL[buf][t4    ][m0 + g];
            aL[mt][1] = AsL[buf][t4    ][m0 + 8 + g];
            aL[mt][2] = AsL[buf][t4 + 4][m0 + g];
            aL[mt][3] = AsL[buf][t4 + 4][m0 + 8 + g];
        }

#pragma unroll
        for (int nt = 0; nt < 8; nt++) {
            int n0 = wn + nt * 8;
            uint32_t bH0 = BsH[buf][t4    ][n0 + g];
            uint32_t bH1 = BsH[buf][t4 + 4][n0 + g];
            uint32_t bL0 = BsL[buf][t4    ][n0 + g];
            uint32_t bL1 = BsL[buf][t4 + 4][n0 + g];
#pragma unroll
            for (int mt = 0; mt < 2; mt++) {
                MMA_TF32(d[mt][nt], aH[mt][0], aH[mt][1], aH[mt][2], aH[mt][3], bH0, bH1);
                MMA_TF32(d[mt][nt], aL[mt][0], aL[mt][1], aL[mt][2], aL[mt][3], bH0, bH1);
                MMA_TF32(d[mt][nt], aH[mt][0], aH[mt][1], aH[mt][2], aH[mt][3], bL0, bL1);
            }
        }

        if (s + 1 < nStage) {
            const int nb = (s + 1) & 1;
            float aa[4] = {av.x, av.y, av.z, av.w};
            float ww[4] = {wv.x, wv.y, wv.z, wv.w};
#pragma unroll
            for (int j = 0; j < 4; j++) {
                uint32_t h = f2tf32(aa[j]);
                AsH[nb][ac + j][ar] = h;
                AsL[nb][ac + j][ar] = f2tf32(aa[j] - __uint_as_float(h));
                uint32_t hw = f2tf32(ww[j]);
                BsH[nb][br][bc + j] = hw;
                BsL[nb][br][bc + j] = f2tf32(ww[j] - __uint_as_float(hw));
            }
            __syncthreads();
        }
    }

    const int rayb = RAYBIAS ? (bm >> 7) * 128 : 0;
#pragma unroll
    for (int mt = 0; mt < 2; mt++) {
#pragma unroll
        for (int nt = 0; nt < 8; nt++) {
            int r0 = bm + wm + mt * 16 + g;
            int c0 = bn + wn + nt * 8 + 2 * t4;
            float b0v = RAYBIAS ? bias[rayb + c0]     : bias[c0];
            float b1v = RAYBIAS ? bias[rayb + c0 + 1] : bias[c0 + 1];
            float v00 = d[mt][nt][0] + b0v;
            float v01 = d[mt][nt][1] + b1v;
            float v10 = d[mt][nt][2] + b0v;
            float v11 = d[mt][nt][3] + b1v;
            if (RELU) {
                v00 = fmaxf(v00, 0.0f); v01 = fmaxf(v01, 0.0f);
                v10 = fmaxf(v10, 0.0f); v11 = fmaxf(v11, 0.0f);
            }
            float2 lo = make_float2(v00, v01);
            float2 hi = make_float2(v10, v11);
            *(float2*)&C[(size_t)r0 * N + c0]       = lo;
            *(float2*)&C[(size_t)(r0 + 8) * N + c0] = hi;
        }
    }
}

// ---------------- thin heads ----------------
__global__ void __launch_bounds__(256) heads_kernel(
    const float* __restrict__ X3, const float* __restrict__ H,
    const float* __restrict__ Ws, const float* __restrict__ bs,
    const float* __restrict__ Wm, const float* __restrict__ bm,
    const float* __restrict__ Wr, const float* __restrict__ br,
    float* __restrict__ RF)
{
    int gw = (blockIdx.x * 256 + threadIdx.x) >> 5;
    int lane = threadIdx.x & 31;
    if (gw >= NS) return;
    const bool hasM = (Wm != nullptr);
    const float* x = X3 + (size_t)gw * 256;
    float s0 = 0.0f, s1 = 0.0f, s2 = 0.0f;
#pragma unroll
    for (int i = 0; i < 8; i++) {
        int c = lane + 32 * i;
        float xv = x[c];
        s0 += xv * Ws[c];
        if (hasM) {
            s1 += xv * Wm[2 * c];
            s2 += xv * Wm[2 * c + 1];
        }
    }
    const float* h = H + (size_t)gw * 128;
    float r = 0.0f, g = 0.0f, b = 0.0f;
#pragma unroll
    for (int i = 0; i < 4; i++) {
        int c = lane + 32 * i;
        float hv = h[c];
        r += hv * Wr[3 * c];
        g += hv * Wr[3 * c + 1];
        b += hv * Wr[3 * c + 2];
    }
#pragma unroll
    for (int o = 16; o > 0; o >>= 1) {
        s0 += __shfl_down_sync(0xffffffffu, s0, o);
        s1 += __shfl_down_sync(0xffffffffu, s1, o);
        s2 += __shfl_down_sync(0xffffffffu, s2, o);
        r  += __shfl_down_sync(0xffffffffu, r, o);
        g  += __shfl_down_sync(0xffffffffu, g, o);
        b  += __shfl_down_sync(0xffffffffu, b, o);
    }
    if (lane == 0) {
        float* f = RF + (size_t)gw * 6;
        f[0] = r + br[0];
        f[1] = g + br[1];
        f[2] = b + br[2];
        f[3] = s0 + bs[0];
        if (hasM) {
            f[4] = s1 + bm[0];
            f[5] = s2 + bm[1];
        }
    }
}

// ---------------- coarse volume render + PDF ingredients ----------------
__global__ void vrender_coarse_kernel(float* __restrict__ out) {
    int r = blockIdx.x * blockDim.x + threadIdx.x;
    if (r >= NRAYS) return;
    float nrm = g_raynorm[r];
    float T = 1.0f, cr = 0.0f, cg = 0.0f, cb = 0.0f;
    for (int i = 0; i < 128; i++) {
        const float* f = g_rf + (size_t)(r * 128 + i) * 6;
        float t0 = 2.0f + 4.0f * ((float)i / 128.0f);
        float t1 = 2.0f + 4.0f * ((float)(i + 1) / 128.0f);
        float sr = fast_sigmoid(f[0]);
        float sg = fast_sigmoid(f[1]);
        float sb = fast_sigmoid(f[2]);
        float sigma = fmaxf(f[3], 0.0f);
        float alpha = 1.0f - __expf(-sigma * (t1 - t0) * nrm);
        float w = alpha * T;
        T *= (1.0f - alpha + 1e-10f);
        cr += w * sr; cg += w * sg; cb += w * sb;
        int si = r * 128 + i;
        g_weights[si] = w;
        float mu = fast_sigmoid(f[4]);
        float ss = (fast_sigmoid(f[5]) + 0.001f) * 2.0f;
        g_mus[si] = mu;
        g_smsig[si] = ss;
        float l = acdf_((0.0f - mu) / ss);
        g_lt[si] = l;
        g_pib[si] = acdf_((1.0f - mu) / ss) - l;
    }
    out[r * 3 + 0] = cr;
    out[r * 3 + 1] = cg;
    out[r * 3 + 2] = cb;
}

// ---------------- per-ray normalized CDF / PDF ----------------
__global__ void cdf_kernel() {
    int r = blockIdx.x * blockDim.x + threadIdx.x;
    if (r >= NRAYS) return;
    float sum = 0.0f;
    for (int i = 0; i < 128; i++) sum += g_weights[r * 128 + i] + 1e-5f;
    float inv = 1.0f / sum;
    g_cdf[r * 129] = 0.0f;
    float run = 0.0f;
    for (int i = 0; i < 128; i++) {
        float w = (g_weights[r * 128 + i] + 1e-5f) * inv;
        g_pdfn[r * 128 + i] = w;
        run += w;
        g_cdf[r * 129 + i + 1] = run;
    }
}

// ---------------- fully parallel inverse-CDF fine sampling ----------------
__global__ void fine_sample_kernel() {
    int t = blockIdx.x * blockDim.x + threadIdx.x;
    if (t >= NRAYS * 129) return;
    int r = t / 129;
    int i = t - r * 129;
    const float step = (1.0f - 1e-5f) / 128.0f;
    float u = step * (float)i;
    const float* cdf = g_cdf + r * 129;
    // rightmost j in [0,128] with cdf[j] <= u, then clip to 127
    int lo = 0, hi = 128;
    while (lo < hi) {
        int mid = (lo + hi + 1) >> 1;
        if (cdf[mid] <= u) lo = mid; else hi = mid - 1;
    }
    int idx = lo < 127 ? lo : 127;
    float pdfv = g_pdfn[r * 128 + idx];
    float frac = (u - cdf[idx]) / fmaxf(pdfv, 1e-10f);
    frac = fminf(fmaxf(frac, 0.0f), 1.0f);
    int si = r * 128 + idx;
    float p = g_lt[si] + frac * g_pib[si];
    p = fminf(fmaxf(p, 1e-5f), 1.0f - 1e-5f);
    float x = g_mus[si] + g_smsig[si] * 1.4142135623730951f * erfinvf(2.0f * p - 1.0f);
    x = fminf(fmaxf(x, 0.0f), 1.0f);
    float b0 = 2.0f + 4.0f * ((float)idx / 128.0f);
    float b1 = 2.0f + 4.0f * ((float)(idx + 1) / 128.0f);
    g_tfine[r * 129 + i] = b0 + x * (b1 - b0);
}

// ---------------- fine volume render: rgb_f, depth_f, acc_f ----------------
__global__ void vrender_fine_kernel(float* __restrict__ out) {
    int r = blockIdx.x * blockDim.x + threadIdx.x;
    if (r >= NRAYS) return;
    float nrm = g_raynorm[r];
    float T = 1.0f, cr = 0.0f, cg = 0.0f, cb = 0.0f, dep = 0.0f, acc = 0.0f;
    for (int i = 0; i < 128; i++) {
        const float* f = g_rf + (size_t)(r * 128 + i) * 6;
        float t0 = g_tfine[r * 129 + i];
        float t1 = g_tfine[r * 129 + i + 1];
        float sr = fast_sigmoid(f[0]);
        float sg = fast_sigmoid(f[1]);
        float sb = fast_sigmoid(f[2]);
        float sigma = fmaxf(f[3], 0.0f);
        float alpha = 1.0f - __expf(-sigma * (t1 - t0) * nrm);
        float w = alpha * T;
        T *= (1.0f - alpha + 1e-10f);
        cr += w * sr; cg += w * sg; cb += w * sb;
        dep += w * 0.5f * (t0 + t1);
        acc += w;
    }
    out[6144 + r * 3 + 0] = cr;
    out[6144 + r * 3 + 1] = cg;
    out[6144 + r * 3 + 2] = cb;
    out[12288 + r] = dep;
    out[14336 + r] = acc;
}

// ---------------- host orchestration ----------------
extern "C" void kernel_launch(void* const* d_in, const int* in_sizes, int n_in,
                              void* d_out, int out_size)
{
    (void)out_size;
    const float* ro = (const float*)d_in[0];
    const float* rd = (const float*)d_in[1];
    const float* rr = (const float*)d_in[2];

    bool sigOrder = (n_in > 15 && in_sizes[15] == 512);
    int fb = sigOrder ? 17 : 15;
    int mb = sigOrder ? 15 : 27;

    const float* cW0 = (const float*)d_in[3];
    const float* cb0 = (const float*)d_in[4];
    const float* cWh = (const float*)d_in[5];
    const float* cbh = (const float*)d_in[6];
    const float* cWs = (const float*)d_in[7];
    const float* cbs = (const float*)d_in[8];
    const float* cWb = (const float*)d_in[9];
    const float* cbb = (const float*)d_in[10];
    const float* cWd = (const float*)d_in[11];
    const float* cbd = (const float*)d_in[12];
    const float* cWr = (const float*)d_in[13];
    const float* cbr = (const float*)d_in[14];
    const float* cWm = (const float*)d_in[mb];
    const float* cbm = (const float*)d_in[mb + 1];
    const float* fW0 = (const float*)d_in[fb + 0];
    const float* fb0 = (const float*)d_in[fb + 1];
    const float* fWh = (const float*)d_in[fb + 2];
    const float* fbh = (const float*)d_in[fb + 3];
    const float* fWs = (const float*)d_in[fb + 4];
    const float* fbs = (const float*)d_in[fb + 5];
    const float* fWb = (const float*)d_in[fb + 6];
    const float* fbb = (const float*)d_in[fb + 7];
    const float* fWd = (const float*)d_in[fb + 8];
    const float* fbd = (const float*)d_in[fb + 9];
    const float* fWr = (const float*)d_in[fb + 10];
    const float* fbr = (const float*)d_in[fb + 11];

    float *p_enc, *p_x0, *p_x1, *p_h, *p_rf, *p_raybias, *p_tfine;
    cudaGetSymbolAddress((void**)&p_enc, g_enc);
    cudaGetSymbolAddress((void**)&p_x0, g_x0);
    cudaGetSymbolAddress((void**)&p_x1, g_x1);
    cudaGetSymbolAddress((void**)&p_h, g_h);
    cudaGetSymbolAddress((void**)&p_rf, g_rf);
    cudaGetSymbolAddress((void**)&p_raybias, g_raybias);
    cudaGetSymbolAddress((void**)&p_tfine, g_tfine);

    float* out = (float*)d_out;
    const dim3 gWide(NS / 128, 2);   // N=256 layers
    const dim3 gNarrow(NS / 128, 1); // N=128 layer

    ray_setup_kernel<<<(NRAYS + 127) / 128, 128>>>(rd);

    // ================= coarse pass =================
    ipe_kernel<<<NS / 128, 128>>>(ro, rd, rr, nullptr);
    ray_bias_kernel<<<NRAYS, 128>>>(cWd, cbd);
    sgemm_tc<true, false><<<gWide, 256>>>(p_enc, cW0, cb0, p_x0, 96, 256);
    sgemm_tc<true, false><<<gWide, 256>>>(p_x0, cWh,          cbh,       p_x1, 256, 256);
    sgemm_tc<true, false><<<gWide, 256>>>(p_x1, cWh + 65536,  cbh + 256, p_x0, 256, 256);
    sgemm_tc<true, false><<<gWide, 256>>>(p_x0, cWh + 131072, cbh + 512, p_x1, 256, 256);
    sgemm_tc<false, false><<<gWide, 256>>>(p_x1, cWb, cbb, p_x0, 256, 256);
    sgemm_tc<true, true><<<gNarrow, 256>>>(p_x0, cWd, p_raybias, p_h, 256, 128);
    heads_kernel<<<NS / 8, 256>>>(p_x1, p_h, cWs, cbs, cWm, cbm, cWr, cbr, p_rf);
    vrender_coarse_kernel<<<(NRAYS + 127) / 128, 128>>>(out);
    cdf_kernel<<<(NRAYS + 127) / 128, 128>>>();
    fine_sample_kernel<<<(NRAYS * 129 + 255) / 256, 256>>>();

    // ================= fine pass =================
    ipe_kernel<<<NS / 128, 128>>>(ro, rd, rr, p_tfine);
    ray_bias_kernel<<<NRAYS, 128>>>(fWd, fbd);
    sgemm_tc<true, false><<<gWide, 256>>>(p_enc, fW0, fb0, p_x0, 96, 256);
    sgemm_tc<true, false><<<gWide, 256>>>(p_x0, fWh,          fbh,       p_x1, 256, 256);
    sgemm_tc<true, false><<<gWide, 256>>>(p_x1, fWh + 65536,  fbh + 256, p_x0, 256, 256);
    sgemm_tc<true, false><<<gWide, 256>>>(p_x0, fWh + 131072, fbh + 512, p_x1, 256, 256);
    sgemm_tc<false, false><<<gWide, 256>>>(p_x1, fWb, fbb, p_x0, 256, 256);
    sgemm_tc<true, true><<<gNarrow, 256>>>(p_x0, fWd, p_raybias, p_h, 256, 128);
    heads_kernel<<<NS / 8, 256>>>(p_x1, p_h, fWs, fbs, nullptr, nullptr, fWr, fbr, p_rf);
    vrender_fine_kernel<<<(NRAYS + 127) / 128, 128>>>(out);
}

// round 7
// speedup vs baseline: 1.6588x; 1.1034x over previous
#include <cuda_runtime.h>
#include <math.h>
#include <stdint.h>
#include <stddef.h>

#define NRAYS 2048
#define NSAMP 128
#define NS (NRAYS * NSAMP)   // 262144 samples per pass

// ---------------- static scratch (no allocations allowed) ----------------
__device__ float g_enc[NRAYS * 96 * 128];   // block-transposed IPE: [blk][k][m]
__device__ float g_rf[NS * 6];              // raw heads per sample
__device__ float g_direnc[NRAYS * 27];
__device__ float g_raynorm[NRAYS];
__device__ float g_raybias[NRAYS * 128];
__device__ float g_weights[NS];
__device__ float g_mus[NS];
__device__ float g_smsig[NS];
__device__ float g_lt[NS];
__device__ float g_pib[NS];
__device__ float g_tfine[NRAYS * 129];
__device__ float g_cdf[NRAYS * 129];
__device__ float g_pdfn[NS];

// fused-kernel smem: act[256][136] floats + BsH[2][8][264] + BsL[2][8][264] u32
#define ACT_WORDS (256 * 136)
#define BBUF_WORDS (2 * 8 * 264)
#define FUSED_SMEM ((ACT_WORDS + 2 * BBUF_WORDS) * 4)

// ---------------- helpers ----------------
__device__ __forceinline__ float fast_sigmoid(float x) {
    return 1.0f / (1.0f + __expf(-x));
}
__device__ __forceinline__ float acdf_(float x) {
    float x3 = x * x * x;
    float z = 0.7978845608028654f * (x + 0.044715f * x3);
    return 1.0f / (1.0f + __expf(-2.0f * z));
}
__device__ __forceinline__ uint32_t f2tf32(float x) {
    uint32_t r;
    asm("cvt.rna.tf32.f32 %0, %1;" : "=r"(r) : "f"(x));
    return r;
}
__device__ __forceinline__ void cp16(void* s, const void* g) {
    uint32_t sa = (uint32_t)__cvta_generic_to_shared(s);
    asm volatile("cp.async.ca.shared.global [%0], [%1], 16;" :: "r"(sa), "l"(g));
}
__device__ __forceinline__ void cp_commit() {
    asm volatile("cp.async.commit_group;" ::: "memory");
}
__device__ __forceinline__ void cp_wait0() {
    asm volatile("cp.async.wait_group 0;" ::: "memory");
}

#define MMA_TF32(d, a0, a1, a2, a3, b0, b1)                                  \
    asm volatile(                                                            \
        "mma.sync.aligned.m16n8k8.row.col.f32.tf32.tf32.f32 "                \
        "{%0,%1,%2,%3}, {%4,%5,%6,%7}, {%8,%9}, {%0,%1,%2,%3};"              \
        : "+f"(d[0]), "+f"(d[1]), "+f"(d[2]), "+f"(d[3])                     \
        : "r"(a0), "r"(a1), "r"(a2), "r"(a3), "r"(b0), "r"(b1))

// ---------------- ray setup ----------------
__global__ void ray_setup_kernel(const float* __restrict__ rd) {
    int r = blockIdx.x * blockDim.x + threadIdx.x;
    if (r >= NRAYS) return;
    float x = rd[r * 3 + 0], y = rd[r * 3 + 1], z = rd[r * 3 + 2];
    float n = sqrtf(x * x + y * y + z * z);
    g_raynorm[r] = n;
    float inv = 1.0f / n;
    float v[3] = {x * inv, y * inv, z * inv};
    float* de = g_direnc + r * 27;
    de[0] = v[0]; de[1] = v[1]; de[2] = v[2];
#pragma unroll
    for (int f = 0; f < 4; f++) {
        float fr = (float)(1 << f);
#pragma unroll
        for (int k = 0; k < 3; k++) {
            float xx = v[k] * fr;
            de[3 + f * 3 + k]  = sinf(xx);
            de[15 + f * 3 + k] = cosf(xx);
        }
    }
}

// per-ray bias for Wd layer: bd[o] + sum_j direnc[j] * Wd[256+j][o]
__global__ void ray_bias_kernel(const float* __restrict__ Wd, const float* __restrict__ bd) {
    int r = blockIdx.x;
    int o = threadIdx.x;
    __shared__ float de[27];
    if (o < 27) de[o] = g_direnc[r * 27 + o];
    __syncthreads();
    float a = bd[o];
#pragma unroll
    for (int j = 0; j < 27; j++) a += de[j] * Wd[(256 + j) * 128 + o];
    g_raybias[r * 128 + o] = a;
}

// ---------------- IPE, block-transposed output [blk][k][m] ----------------
__global__ void ipe_kernel(const float* __restrict__ ro, const float* __restrict__ rd,
                           const float* __restrict__ rr, const float* __restrict__ tsrc) {
    int s = blockIdx.x * blockDim.x + threadIdx.x;
    if (s >= NS) return;
    int ray = s >> 7, i = s & 127;
    float t0, t1;
    if (tsrc) {
        t0 = tsrc[ray * 129 + i];
        t1 = tsrc[ray * 129 + i + 1];
    } else {
        t0 = 2.0f + 4.0f * ((float)i / 128.0f);
        t1 = 2.0f + 4.0f * ((float)(i + 1) / 128.0f);
    }
    float c  = 0.5f * (t0 + t1);
    float dd = 0.5f * (t1 - t0);
    float d2s = dd * dd;
    float d4  = d2s * d2s;
    float c2  = c * c;
    float denom = 3.0f * c2 + d2s;
    float t_mean = c + 2.0f * c * d2s / denom;
    float t_var  = d2s * (1.0f / 3.0f) - (4.0f / 15.0f) * (d4 * (12.0f * c2 - d2s)) / (denom * denom);
    float rrv = rr[ray];
    float r_var = rrv * rrv * (c2 * 0.25f + (5.0f / 12.0f) * d2s - (4.0f / 15.0f) * d4 / denom);

    float rdv[3] = {rd[ray * 3 + 0], rd[ray * 3 + 1], rd[ray * 3 + 2]};
    float rov[3] = {ro[ray * 3 + 0], ro[ray * 3 + 1], ro[ray * 3 + 2]};
    float dn2 = rdv[0] * rdv[0] + rdv[1] * rdv[1] + rdv[2] * rdv[2];
    float invd2 = 1.0f / fmaxf(dn2, 1e-10f);
    float mean[3], cov[3];
#pragma unroll
    for (int k = 0; k < 3; k++) {
        mean[k] = rov[k] + rdv[k] * t_mean;
        float dok = rdv[k] * rdv[k];
        cov[k] = t_var * dok + r_var * (1.0f - dok * invd2);
    }

    float* e = g_enc + (size_t)ray * 96 * 128;   // block base
    int m = i;
    float scale = 1.0f;
#pragma unroll 4
    for (int deg = 0; deg < 16; deg++) {
        float sc2 = scale * scale;
#pragma unroll
        for (int k = 0; k < 3; k++) {
            int idx = deg * 3 + k;
            float sv, cv;
            float yv = cov[k] * sc2;
            if (yv > 60.0f) {
                sv = 0.0f; cv = 0.0f;
            } else {
                float att = __expf(-0.5f * yv);
                float y = mean[k] * scale;
                double kd = rint((double)y * 0.15915494309189535);
                float rp = (float)((double)y - kd * 6.283185307179586);
                sv = __sinf(rp) * att;
                cv = __cosf(rp) * att;
            }
            e[(size_t)idx * 128 + m]        = sv;
            e[(size_t)(48 + idx) * 128 + m] = cv;
        }
        scale *= 2.0f;
    }
}

// ---------------- fused-MLP layer (in-smem activations) ----------------
// NT: n-tiles per warp (8 -> N=256, 4 -> N=128). Warp layout 4(m) x 4(n).
// A raw fp32 in act[k][m] (stride 136); split to tf32 hi/lo at fragment load.
// W streamed from global, split hi/lo at store into BsH/BsL (stride 264).
// Epilogue writes TRANSPOSED into act[n][m].
#define BSH(b, k, n) Bb[((b) * 8 + (k)) * 264 + (n)]
#define BSL(b, k, n) Bb[2112 * 2 + ((b) * 8 + (k)) * 264 + (n)]

template<int NT, bool RELU, bool RB>
__device__ __forceinline__ void run_layer(
    float (*act)[136], uint32_t* Bb,
    const float* __restrict__ Wl, const float* __restrict__ bias,
    int K, int tid, int wid, int lane)
{
    const int NCOLS = NT * 32;
    const int wm = (wid & 3) * 32;
    const int wn = (wid >> 2) * (NT * 8);
    const int g  = lane >> 2;
    const int t4 = lane & 3;

    const int cpr  = NCOLS / 4;            // float4 chunks per W row
    const int brow = tid / cpr;
    const int bcol = (tid % cpr) * 4;
    const bool bload = (brow < 8);
    const float* Wp = Wl + (size_t)brow * NCOLS + bcol;

    float d[2][NT][4];
#pragma unroll
    for (int mt = 0; mt < 2; mt++)
#pragma unroll
        for (int nt = 0; nt < NT; nt++)
#pragma unroll
            for (int q = 0; q < 4; q++) d[mt][nt][q] = 0.0f;

    const int nStage = K >> 3;

    float4 wv = make_float4(0.f, 0.f, 0.f, 0.f);
    if (bload) wv = *(const float4*)Wp;
    // stash stage 0
    if (bload) {
        float ww[4] = {wv.x, wv.y, wv.z, wv.w};
        uint4 hv, lv;
        uint32_t* hp = &hv.x; uint32_t* lp = &lv.x;
#pragma unroll
        for (int j = 0; j < 4; j++) {
            uint32_t h = f2tf32(ww[j]);
            hp[j] = h;
            lp[j] = f2tf32(ww[j] - __uint_as_float(h));
        }
        *(uint4*)&BSH(0, brow, bcol) = hv;
        *(uint4*)&BSL(0, brow, bcol) = lv;
    }
    __syncthreads();

    for (int s = 0; s < nStage; ++s) {
        const int buf = s & 1;
        if (s + 1 < nStage && bload)
            wv = *(const float4*)(Wp + (size_t)(s + 1) * 8 * NCOLS);

        const int k0 = s * 8;
        uint32_t aH[2][4], aL[2][4];
#pragma unroll
        for (int mt = 0; mt < 2; mt++) {
            int m0 = wm + mt * 16;
            float x0 = act[k0 + t4][m0 + g];
            float x1 = act[k0 + t4][m0 + 8 + g];
            float x2 = act[k0 + t4 + 4][m0 + g];
            float x3 = act[k0 + t4 + 4][m0 + 8 + g];
            uint32_t h;
            h = f2tf32(x0); aH[mt][0] = h; aL[mt][0] = f2tf32(x0 - __uint_as_float(h));
            h = f2tf32(x1); aH[mt][1] = h; aL[mt][1] = f2tf32(x1 - __uint_as_float(h));
            h = f2tf32(x2); aH[mt][2] = h; aL[mt][2] = f2tf32(x2 - __uint_as_float(h));
            h = f2tf32(x3); aH[mt][3] = h; aL[mt][3] = f2tf32(x3 - __uint_as_float(h));
        }

#pragma unroll
        for (int nt = 0; nt < NT; nt++) {
            int n0 = wn + nt * 8;
            uint32_t bH0 = BSH(buf, t4,     n0 + g);
            uint32_t bH1 = BSH(buf, t4 + 4, n0 + g);
            uint32_t bL0 = BSL(buf, t4,     n0 + g);
            uint32_t bL1 = BSL(buf, t4 + 4, n0 + g);
#pragma unroll
            for (int mt = 0; mt < 2; mt++) {
                MMA_TF32(d[mt][nt], aH[mt][0], aH[mt][1], aH[mt][2], aH[mt][3], bH0, bH1);
                MMA_TF32(d[mt][nt], aL[mt][0], aL[mt][1], aL[mt][2], aL[mt][3], bH0, bH1);
                MMA_TF32(d[mt][nt], aH[mt][0], aH[mt][1], aH[mt][2], aH[mt][3], bL0, bL1);
            }
        }

        if (s + 1 < nStage) {
            const int nb = (s + 1) & 1;
            if (bload) {
                float ww[4] = {wv.x, wv.y, wv.z, wv.w};
                uint4 hv, lv;
                uint32_t* hp = &hv.x; uint32_t* lp = &lv.x;
#pragma unroll
                for (int j = 0; j < 4; j++) {
                    uint32_t h = f2tf32(ww[j]);
                    hp[j] = h;
                    lp[j] = f2tf32(ww[j] - __uint_as_float(h));
                }
                *(uint4*)&BSH(nb, brow, bcol) = hv;
                *(uint4*)&BSL(nb, brow, bcol) = lv;
            }
            __syncthreads();
        }
    }

    __syncthreads();   // all fragment reads of act done

    // transposed epilogue: act[col][row] = activation(value + bias)
#pragma unroll
    for (int mt = 0; mt < 2; mt++) {
#pragma unroll
        for (int nt = 0; nt < NT; nt++) {
            int r0 = wm + mt * 16 + g;
            int c0 = wn + nt * 8 + 2 * t4;
            float b0v = bias[c0];
            float b1v = bias[c0 + 1];
            float v00 = d[mt][nt][0] + b0v;
            float v01 = d[mt][nt][1] + b1v;
            float v10 = d[mt][nt][2] + b0v;
            float v11 = d[mt][nt][3] + b1v;
            if (RELU) {
                v00 = fmaxf(v00, 0.0f); v01 = fmaxf(v01, 0.0f);
                v10 = fmaxf(v10, 0.0f); v11 = fmaxf(v11, 0.0f);
            }
            act[c0][r0]         = v00;
            act[c0 + 1][r0]     = v01;
            act[c0][r0 + 8]     = v10;
            act[c0 + 1][r0 + 8] = v11;
        }
    }
    __syncthreads();
}

// ---------------- fused MLP: one block = one ray (128 samples) ----------------
template<bool COARSE>
__global__ void __launch_bounds__(512, 1) fused_mlp(
    const float* __restrict__ enc_t,
    const float* __restrict__ W0, const float* __restrict__ b0,
    const float* __restrict__ Wh, const float* __restrict__ bh,
    const float* __restrict__ Ws, const float* __restrict__ bs,
    const float* __restrict__ Wm, const float* __restrict__ bm,
    const float* __restrict__ Wb, const float* __restrict__ bb,
    const float* __restrict__ Wd, const float* __restrict__ rbias_all,
    const float* __restrict__ Wr, const float* __restrict__ br,
    float* __restrict__ RF)
{
    extern __shared__ float smem[];
    float (*act)[136] = (float(*)[136])smem;
    uint32_t* Bb = (uint32_t*)(smem + ACT_WORDS);

    const int tid  = threadIdx.x;
    const int wid  = tid >> 5;
    const int lane = tid & 31;
    const int blk  = blockIdx.x;

    // load enc tile [96][128] into act
    {
        const float* ebase = enc_t + (size_t)blk * 96 * 128;
        for (int i = tid; i < 96 * 32; i += 512) {
            int k = i >> 5, m4 = (i & 31) * 4;
            cp16(&act[k][m4], ebase + k * 128 + m4);
        }
        cp_commit(); cp_wait0();
    }
    __syncthreads();

    run_layer<8, true, false>(act, Bb, W0, b0, 96, tid, wid, lane);
    for (int l = 0; l < 3; l++)
        run_layer<8, true, false>(act, Bb, Wh + l * 65536, bh + l * 256, 256, tid, wid, lane);

    // heads from x1 (= act): sigma (+ mu/sig for coarse)
    float* rf = RF + (size_t)blk * 128 * 6;
    if (wid < 4) {
        int m = wid * 32 + lane;
        float s0 = 0.0f, s1 = 0.0f, s2 = 0.0f;
        for (int k = 0; k < 256; k++) {
            float xv = act[k][m];
            s0 += xv * __ldg(Ws + k);
            if (COARSE) {
                s1 += xv * __ldg(Wm + 2 * k);
                s2 += xv * __ldg(Wm + 2 * k + 1);
            }
        }
        rf[m * 6 + 3] = s0 + __ldg(bs);
        if (COARSE) {
            rf[m * 6 + 4] = s1 + __ldg(bm);
            rf[m * 6 + 5] = s2 + __ldg(bm + 1);
        }
    }
    __syncthreads();

    run_layer<8, false, false>(act, Bb, Wb, bb, 256, tid, wid, lane);
    run_layer<4, true, false>(act, Bb, Wd, rbias_all + (size_t)blk * 128, 256, tid, wid, lane);

    // rgb head from h (= act rows 0..127)
    if (wid < 4) {
        int m = wid * 32 + lane;
        float r = 0.0f, gg = 0.0f, b = 0.0f;
        for (int k = 0; k < 128; k++) {
            float hv = act[k][m];
            r  += hv * __ldg(Wr + 3 * k);
            gg += hv * __ldg(Wr + 3 * k + 1);
            b  += hv * __ldg(Wr + 3 * k + 2);
        }
        rf[m * 6 + 0] = r  + __ldg(br);
        rf[m * 6 + 1] = gg + __ldg(br + 1);
        rf[m * 6 + 2] = b  + __ldg(br + 2);
    }
}

// ---------------- coarse volume render + PDF ingredients ----------------
__global__ void vrender_coarse_kernel(float* __restrict__ out) {
    int r = blockIdx.x * blockDim.x + threadIdx.x;
    if (r >= NRAYS) return;
    float nrm = g_raynorm[r];
    float T = 1.0f, cr = 0.0f, cg = 0.0f, cb = 0.0f;
    for (int i = 0; i < 128; i++) {
        const float* f = g_rf + (size_t)(r * 128 + i) * 6;
        float t0 = 2.0f + 4.0f * ((float)i / 128.0f);
        float t1 = 2.0f + 4.0f * ((float)(i + 1) / 128.0f);
        float sr = fast_sigmoid(f[0]);
        float sg = fast_sigmoid(f[1]);
        float sb = fast_sigmoid(f[2]);
        float sigma = fmaxf(f[3], 0.0f);
        float alpha = 1.0f - __expf(-sigma * (t1 - t0) * nrm);
        float w = alpha * T;
        T *= (1.0f - alpha + 1e-10f);
        cr += w * sr; cg += w * sg; cb += w * sb;
        int si = r * 128 + i;
        g_weights[si] = w;
        float mu = fast_sigmoid(f[4]);
        float ss = (fast_sigmoid(f[5]) + 0.001f) * 2.0f;
        g_mus[si] = mu;
        g_smsig[si] = ss;
        float l = acdf_((0.0f - mu) / ss);
        g_lt[si] = l;
        g_pib[si] = acdf_((1.0f - mu) / ss) - l;
    }
    out[r * 3 + 0] = cr;
    out[r * 3 + 1] = cg;
    out[r * 3 + 2] = cb;
}

// ---------------- per-ray normalized CDF / PDF ----------------
__global__ void cdf_kernel() {
    int r = blockIdx.x * blockDim.x + threadIdx.x;
    if (r >= NRAYS) return;
    float sum = 0.0f;
    for (int i = 0; i < 128; i++) sum += g_weights[r * 128 + i] + 1e-5f;
    float inv = 1.0f / sum;
    g_cdf[r * 129] = 0.0f;
    float run = 0.0f;
    for (int i = 0; i < 128; i++) {
        float w = (g_weights[r * 128 + i] + 1e-5f) * inv;
        g_pdfn[r * 128 + i] = w;
        run += w;
        g_cdf[r * 129 + i + 1] = run;
    }
}

// ---------------- parallel inverse-CDF fine sampling ----------------
__global__ void fine_sample_kernel() {
    int t = blockIdx.x * blockDim.x + threadIdx.x;
    if (t >= NRAYS * 129) return;
    int r = t / 129;
    int i = t - r * 129;
    const float step = (1.0f - 1e-5f) / 128.0f;
    float u = step * (float)i;
    const float* cdf = g_cdf + r * 129;
    int lo = 0, hi = 128;
    while (lo < hi) {
        int mid = (lo + hi + 1) >> 1;
        if (cdf[mid] <= u) lo = mid; else hi = mid - 1;
    }
    int idx = lo < 127 ? lo : 127;
    float pdfv = g_pdfn[r * 128 + idx];
    float frac = (u - cdf[idx]) / fmaxf(pdfv, 1e-10f);
    frac = fminf(fmaxf(frac, 0.0f), 1.0f);
    int si = r * 128 + idx;
    float p = g_lt[si] + frac * g_pib[si];
    p = fminf(fmaxf(p, 1e-5f), 1.0f - 1e-5f);
    float x = g_mus[si] + g_smsig[si] * 1.4142135623730951f * erfinvf(2.0f * p - 1.0f);
    x = fminf(fmaxf(x, 0.0f), 1.0f);
    float b0 = 2.0f + 4.0f * ((float)idx / 128.0f);
    float b1 = 2.0f + 4.0f * ((float)(idx + 1) / 128.0f);
    g_tfine[r * 129 + i] = b0 + x * (b1 - b0);
}

// ---------------- fine volume render ----------------
__global__ void vrender_fine_kernel(float* __restrict__ out) {
    int r = blockIdx.x * blockDim.x + threadIdx.x;
    if (r >= NRAYS) return;
    float nrm = g_raynorm[r];
    float T = 1.0f, cr = 0.0f, cg = 0.0f, cb = 0.0f, dep = 0.0f, acc = 0.0f;
    for (int i = 0; i < 128; i++) {
        const float* f = g_rf + (size_t)(r * 128 + i) * 6;
        float t0 = g_tfine[r * 129 + i];
        float t1 = g_tfine[r * 129 + i + 1];
        float sr = fast_sigmoid(f[0]);
        float sg = fast_sigmoid(f[1]);
        float sb = fast_sigmoid(f[2]);
        float sigma = fmaxf(f[3], 0.0f);
        float alpha = 1.0f - __expf(-sigma * (t1 - t0) * nrm);
        float w = alpha * T;
        T *= (1.0f - alpha + 1e-10f);
        cr += w * sr; cg += w * sg; cb += w * sb;
        dep += w * 0.5f * (t0 + t1);
        acc += w;
    }
    out[6144 + r * 3 + 0] = cr;
    out[6144 + r * 3 + 1] = cg;
    out[6144 + r * 3 + 2] = cb;
    out[12288 + r] = dep;
    out[14336 + r] = acc;
}

// ---------------- host orchestration ----------------
extern "C" void kernel_launch(void* const* d_in, const int* in_sizes, int n_in,
                              void* d_out, int out_size)
{
    (void)out_size;
    const float* ro = (const float*)d_in[0];
    const float* rd = (const float*)d_in[1];
    const float* rr = (const float*)d_in[2];

    bool sigOrder = (n_in > 15 && in_sizes[15] == 512);
    int fb = sigOrder ? 17 : 15;
    int mb = sigOrder ? 15 : 27;

    const float* cW0 = (const float*)d_in[3];
    const float* cb0 = (const float*)d_in[4];
    const float* cWh = (const float*)d_in[5];
    const float* cbh = (const float*)d_in[6];
    const float* cWs = (const float*)d_in[7];
    const float* cbs = (const float*)d_in[8];
    const float* cWb = (const float*)d_in[9];
    const float* cbb = (const float*)d_in[10];
    const float* cWd = (const float*)d_in[11];
    const float* cbd = (const float*)d_in[12];
    const float* cWr = (const float*)d_in[13];
    const float* cbr = (const float*)d_in[14];
    const float* cWm = (const float*)d_in[mb];
    const float* cbm = (const float*)d_in[mb + 1];
    const float* fW0 = (const float*)d_in[fb + 0];
    const float* fb0 = (const float*)d_in[fb + 1];
    const float* fWh = (const float*)d_in[fb + 2];
    const float* fbh = (const float*)d_in[fb + 3];
    const float* fWs = (const float*)d_in[fb + 4];
    const float* fbs = (const float*)d_in[fb + 5];
    const float* fWb = (const float*)d_in[fb + 6];
    const float* fbb = (const float*)d_in[fb + 7];
    const float* fWd = (const float*)d_in[fb + 8];
    const float* fbd = (const float*)d_in[fb + 9];
    const float* fWr = (const float*)d_in[fb + 10];
    const float* fbr = (const float*)d_in[fb + 11];

    float *p_enc, *p_rf, *p_raybias, *p_tfine;
    cudaGetSymbolAddress((void**)&p_enc, g_enc);
    cudaGetSymbolAddress((void**)&p_rf, g_rf);
    cudaGetSymbolAddress((void**)&p_raybias, g_raybias);
    cudaGetSymbolAddress((void**)&p_tfine, g_tfine);

    cudaFuncSetAttribute(fused_mlp<true>,  cudaFuncAttributeMaxDynamicSharedMemorySize, FUSED_SMEM);
    cudaFuncSetAttribute(fused_mlp<false>, cudaFuncAttributeMaxDynamicSharedMemorySize, FUSED_SMEM);

    float* out = (float*)d_out;

    ray_setup_kernel<<<(NRAYS + 127) / 128, 128>>>(rd);

    // ================= coarse pass =================
    ipe_kernel<<<NS / 128, 128>>>(ro, rd, rr, nullptr);
    ray_bias_kernel<<<NRAYS, 128>>>(cWd, cbd);
    fused_mlp<true><<<NRAYS, 512, FUSED_SMEM>>>(
        p_enc, cW0, cb0, cWh, cbh, cWs, cbs, cWm, cbm,
        cWb, cbb, cWd, p_raybias, cWr, cbr, p_rf);
    vrender_coarse_kernel<<<(NRAYS + 127) / 128, 128>>>(out);
    cdf_kernel<<<(NRAYS + 127) / 128, 128>>>();
    fine_sample_kernel<<<(NRAYS * 129 + 255) / 256, 256>>>();

    // ================= fine pass =================
    ipe_kernel<<<NS / 128, 128>>>(ro, rd, rr, p_tfine);
    ray_bias_kernel<<<NRAYS, 128>>>(fWd, fbd);
    fused_mlp<false><<<NRAYS, 512, FUSED_SMEM>>>(
        p_enc, fW0, fb0, fWh, fbh, fWs, fbs, nullptr, nullptr,
        fWb, fbb, fWd, p_raybias, fWr, fbr, p_rf);
    vrender_fine_kernel<<<(NRAYS + 127) / 128, 128>>>(out);
}

// round 9
// speedup vs baseline: 2.9126x; 1.7559x over previous
#include <cuda_runtime.h>
#include <math.h>
#include <stdint.h>
#include <stddef.h>

#define NRAYS 2048
#define NSAMP 128
#define NS (NRAYS * NSAMP)   // 262144 samples per pass

// ---------------- static scratch (no allocations allowed) ----------------
__device__ float g_enc[NRAYS * 96 * 128];   // block-transposed IPE: [blk][k][m]
__device__ float g_rf[NS * 6];              // raw heads per sample
__device__ float g_direnc[NRAYS * 27];
__device__ float g_raynorm[NRAYS];
__device__ float g_raybias[NRAYS * 128];
__device__ float g_weights[NS];
__device__ float g_mus[NS];
__device__ float g_smsig[NS];
__device__ float g_lt[NS];
__device__ float g_pib[NS];
__device__ float g_tfine[NRAYS * 129];
__device__ float g_cdf[NRAYS * 129];
__device__ float g_pdfn[NS];

// fused-kernel smem layout:
//   act  : 256 x 132 fp32                    (135168 B)
//   BpkH : 2 buf x 8 k2 x 264 u32 (bf16x2)   ( 16896 B)
//   BpkL : same                              ( 16896 B)
#define ACT_STRIDE 132
#define ACT_WORDS (256 * ACT_STRIDE)
#define BPK_WORDS (2 * 8 * 264)
#define FUSED_SMEM ((ACT_WORDS + 2 * BPK_WORDS) * 4)   // 168960 B

// ---------------- helpers ----------------
__device__ __forceinline__ float fast_sigmoid(float x) {
    return 1.0f / (1.0f + __expf(-x));
}
__device__ __forceinline__ float acdf_(float x) {
    float x3 = x * x * x;
    float z = 0.7978845608028654f * (x + 0.044715f * x3);
    return 1.0f / (1.0f + __expf(-2.0f * z));
}
// pack {lower = bf16(x0) [k even], upper = bf16(x1) [k odd]}
__device__ __forceinline__ uint32_t pack_bf16x2(float x0, float x1) {
    uint32_t d;
    asm("cvt.rn.bf16x2.f32 %0, %1, %2;" : "=r"(d) : "f"(x1), "f"(x0));
    return d;
}
// split pair (x0, x1) into bf16 hi-pack + bf16 lo-pack (residuals)
__device__ __forceinline__ void split_pair(float x0, float x1, uint32_t& hpk, uint32_t& lpk) {
    hpk = pack_bf16x2(x0, x1);
    float h0 = __uint_as_float(hpk << 16);
    float h1 = __uint_as_float(hpk & 0xffff0000u);
    lpk = pack_bf16x2(x0 - h0, x1 - h1);
}
__device__ __forceinline__ void cp16(void* s, const void* g) {
    uint32_t sa = (uint32_t)__cvta_generic_to_shared(s);
    asm volatile("cp.async.ca.shared.global [%0], [%1], 16;" :: "r"(sa), "l"(g));
}
__device__ __forceinline__ void cp_commit() {
    asm volatile("cp.async.commit_group;" ::: "memory");
}
__device__ __forceinline__ void cp_wait0() {
    asm volatile("cp.async.wait_group 0;" ::: "memory");
}

#define MMA_BF16(d, a0, a1, a2, a3, b0, b1)                                  \
    asm volatile(                                                            \
        "mma.sync.aligned.m16n8k16.row.col.f32.bf16.bf16.f32 "               \
        "{%0,%1,%2,%3}, {%4,%5,%6,%7}, {%8,%9}, {%0,%1,%2,%3};"              \
        : "+f"(d[0]), "+f"(d[1]), "+f"(d[2]), "+f"(d[3])                     \
        : "r"(a0), "r"(a1), "r"(a2), "r"(a3), "r"(b0), "r"(b1))

// ---------------- ray setup ----------------
__global__ void ray_setup_kernel(const float* __restrict__ rd) {
    int r = blockIdx.x * blockDim.x + threadIdx.x;
    if (r >= NRAYS) return;
    float x = rd[r * 3 + 0], y = rd[r * 3 + 1], z = rd[r * 3 + 2];
    float n = sqrtf(x * x + y * y + z * z);
    g_raynorm[r] = n;
    float inv = 1.0f / n;
    float v[3] = {x * inv, y * inv, z * inv};
    float* de = g_direnc + r * 27;
    de[0] = v[0]; de[1] = v[1]; de[2] = v[2];
#pragma unroll
    for (int f = 0; f < 4; f++) {
        float fr = (float)(1 << f);
#pragma unroll
        for (int k = 0; k < 3; k++) {
            float xx = v[k] * fr;
            de[3 + f * 3 + k]  = sinf(xx);
            de[15 + f * 3 + k] = cosf(xx);
        }
    }
}

// per-ray bias for Wd layer: bd[o] + sum_j direnc[j] * Wd[256+j][o]
__global__ void ray_bias_kernel(const float* __restrict__ Wd, const float* __restrict__ bd) {
    int r = blockIdx.x;
    int o = threadIdx.x;
    __shared__ float de[27];
    if (o < 27) de[o] = g_direnc[r * 27 + o];
    __syncthreads();
    float a = bd[o];
#pragma unroll
    for (int j = 0; j < 27; j++) a += de[j] * Wd[(256 + j) * 128 + o];
    g_raybias[r * 128 + o] = a;
}

// ---------------- IPE, block-transposed output [blk][k][m] ----------------
__global__ void ipe_kernel(const float* __restrict__ ro, const float* __restrict__ rd,
                           const float* __restrict__ rr, const float* __restrict__ tsrc) {
    int s = blockIdx.x * blockDim.x + threadIdx.x;
    if (s >= NS) return;
    int ray = s >> 7, i = s & 127;
    float t0, t1;
    if (tsrc) {
        t0 = tsrc[ray * 129 + i];
        t1 = tsrc[ray * 129 + i + 1];
    } else {
        t0 = 2.0f + 4.0f * ((float)i / 128.0f);
        t1 = 2.0f + 4.0f * ((float)(i + 1) / 128.0f);
    }
    float c  = 0.5f * (t0 + t1);
    float dd = 0.5f * (t1 - t0);
    float d2s = dd * dd;
    float d4  = d2s * d2s;
    float c2  = c * c;
    float denom = 3.0f * c2 + d2s;
    float t_mean = c + 2.0f * c * d2s / denom;
    float t_var  = d2s * (1.0f / 3.0f) - (4.0f / 15.0f) * (d4 * (12.0f * c2 - d2s)) / (denom * denom);
    float rrv = rr[ray];
    float r_var = rrv * rrv * (c2 * 0.25f + (5.0f / 12.0f) * d2s - (4.0f / 15.0f) * d4 / denom);

    float rdv[3] = {rd[ray * 3 + 0], rd[ray * 3 + 1], rd[ray * 3 + 2]};
    float rov[3] = {ro[ray * 3 + 0], ro[ray * 3 + 1], ro[ray * 3 + 2]};
    float dn2 = rdv[0] * rdv[0] + rdv[1] * rdv[1] + rdv[2] * rdv[2];
    float invd2 = 1.0f / fmaxf(dn2, 1e-10f);
    float mean[3], cov[3];
#pragma unroll
    for (int k = 0; k < 3; k++) {
        mean[k] = rov[k] + rdv[k] * t_mean;
        float dok = rdv[k] * rdv[k];
        cov[k] = t_var * dok + r_var * (1.0f - dok * invd2);
    }

    float* e = g_enc + (size_t)ray * 96 * 128;
    int m = i;
    float scale = 1.0f;
#pragma unroll 4
    for (int deg = 0; deg < 16; deg++) {
        float sc2 = scale * scale;
#pragma unroll
        for (int k = 0; k < 3; k++) {
            int idx = deg * 3 + k;
            float sv, cv;
            float yv = cov[k] * sc2;
            if (yv > 60.0f) {
                sv = 0.0f; cv = 0.0f;
            } else {
                float att = __expf(-0.5f * yv);
                float y = mean[k] * scale;
                double kd = rint((double)y * 0.15915494309189535);
                float rp = (float)((double)y - kd * 6.283185307179586);
                sv = __sinf(rp) * att;
                cv = __cosf(rp) * att;
            }
            e[(size_t)idx * 128 + m]        = sv;
            e[(size_t)(48 + idx) * 128 + m] = cv;
        }
        scale *= 2.0f;
    }
}

// ---------------- fused-MLP layer, bf16x3 m16n8k16 ----------------
// Warp layout: 8(m) x 2(n); warp tile m16 x (NT*8).  N total = NT*16.
// act[k][m] raw fp32, stride 132 (conflict-free for k-pair loads).
// W streamed, split hi/lo bf16x2-packed by k-pairs at stash time.
template<int NT, bool RELU>
__device__ __forceinline__ void run_layer(
    float* __restrict__ act, uint32_t* __restrict__ BbH, uint32_t* __restrict__ BbL,
    const float* __restrict__ Wl, const float* __restrict__ bias,
    int K, int tid, int wid, int lane)
{
    constexpr int NCOLS = NT * 16;
    constexpr int PER = (8 * NCOLS) / 512;   // packed words per thread per stage
    const int wm = (wid & 7) * 16;
    const int wn = (wid >> 3) * (NT * 8);
    const int g  = lane >> 2;
    const int t4 = lane & 3;

    const int idx0 = tid * PER;
    const int k2   = idx0 / NCOLS;           // 0..7
    const int nn   = idx0 % NCOLS;
    const float* Wr0 = Wl + (size_t)(2 * k2) * NCOLS + nn;
    const float* Wr1 = Wr0 + NCOLS;
    uint32_t* stH = BbH + k2 * 264 + nn;
    uint32_t* stL = BbL + k2 * 264 + nn;

    float d[NT][4];
#pragma unroll
    for (int nt = 0; nt < NT; nt++)
#pragma unroll
        for (int q = 0; q < 4; q++) d[nt][q] = 0.0f;

    const int nStage = K >> 4;

    float p0[PER], p1[PER];

    auto loadW = [&](int s) {
        const float* a0 = Wr0 + (size_t)s * 16 * NCOLS;
        const float* a1 = Wr1 + (size_t)s * 16 * NCOLS;
        if constexpr (PER == 4) {
            float4 u = *(const float4*)a0; p0[0]=u.x; p0[1]=u.y; p0[2]=u.z; p0[3]=u.w;
            float4 v = *(const float4*)a1; p1[0]=v.x; p1[1]=v.y; p1[2]=v.z; p1[3]=v.w;
        } else {
            float2 u = *(const float2*)a0; p0[0]=u.x; p0[1]=u.y;
            float2 v = *(const float2*)a1; p1[0]=v.x; p1[1]=v.y;
        }
    };
    auto stash = [&](int b) {
        uint32_t h[PER], l[PER];
#pragma unroll
        for (int j = 0; j < PER; j++) split_pair(p0[j], p1[j], h[j], l[j]);
        if constexpr (PER == 4) {
            *(uint4*)(stH + b * 2112) = make_uint4(h[0], h[1], h[2], h[3]);
            *(uint4*)(stL + b * 2112) = make_uint4(l[0], l[1], l[2], l[3]);
        } else {
            *(uint2*)(stH + b * 2112) = make_uint2(h[0], h[1]);
            *(uint2*)(stL + b * 2112) = make_uint2(l[0], l[1]);
        }
    };

    loadW(0);
    stash(0);
    __syncthreads();

    for (int s = 0; s < nStage; ++s) {
        const int buf = s & 1;
        if (s + 1 < nStage) loadW(s + 1);

        // A fragments: k-pairs split to bf16 hi/lo at load
        uint32_t aH[4], aL[4];
        {
            const float* A0 = act + (size_t)(s * 16 + 2 * t4) * ACT_STRIDE;
            const float* A8 = A0 + 8 * ACT_STRIDE;
            const int ma = wm + g, mb = ma + 8;
            split_pair(A0[ma], A0[ACT_STRIDE + ma], aH[0], aL[0]);
            split_pair(A0[mb], A0[ACT_STRIDE + mb], aH[1], aL[1]);
            split_pair(A8[ma], A8[ACT_STRIDE + ma], aH[2], aL[2]);
            split_pair(A8[mb], A8[ACT_STRIDE + mb], aH[3], aL[3]);
        }

        const uint32_t* bh = BbH + buf * 2112 + t4 * 264;
        const uint32_t* bl = BbL + buf * 2112 + t4 * 264;
#pragma unroll
        for (int nt = 0; nt < NT; nt++) {
            const int n0 = wn + nt * 8 + g;
            uint32_t bH0 = bh[n0];
            uint32_t bH1 = bh[4 * 264 + n0];
            uint32_t bL0 = bl[n0];
            uint32_t bL1 = bl[4 * 264 + n0];
            MMA_BF16(d[nt], aH[0], aH[1], aH[2], aH[3], bH0, bH1);
            MMA_BF16(d[nt], aL[0], aL[1], aL[2], aL[3], bH0, bH1);
            MMA_BF16(d[nt], aH[0], aH[1], aH[2], aH[3], bL0, bL1);
        }

        if (s + 1 < nStage) {
            stash(buf ^ 1);
            __syncthreads();
        }
    }

    __syncthreads();   // all act reads complete before overwrite

    // transposed epilogue: act[col][row] = activation(value + bias)
#pragma unroll
    for (int nt = 0; nt < NT; nt++) {
        const int c0 = wn + nt * 8 + 2 * t4;
        const int r0 = wm + g;
        float b0v = bias[c0], b1v = bias[c0 + 1];
        float v0 = d[nt][0] + b0v;
        float v1 = d[nt][1] + b1v;
        float v2 = d[nt][2] + b0v;
        float v3 = d[nt][3] + b1v;
        if (RELU) {
            v0 = fmaxf(v0, 0.0f); v1 = fmaxf(v1, 0.0f);
            v2 = fmaxf(v2, 0.0f); v3 = fmaxf(v3, 0.0f);
        }
        act[(size_t)c0 * ACT_STRIDE + r0]           = v0;
        act[(size_t)(c0 + 1) * ACT_STRIDE + r0]     = v1;
        act[(size_t)c0 * ACT_STRIDE + r0 + 8]       = v2;
        act[(size_t)(c0 + 1) * ACT_STRIDE + r0 + 8] = v3;
    }
    __syncthreads();
}

// ---------------- fused MLP: one block = one ray (128 samples) ----------------
template<bool COARSE>
__global__ void __launch_bounds__(512, 1) fused_mlp(
    const float* __restrict__ enc_t,
    const float* __restrict__ W0, const float* __restrict__ b0,
    const float* __restrict__ Wh, const float* __restrict__ bh,
    const float* __restrict__ Ws, const float* __restrict__ bs,
    const float* __restrict__ Wm, const float* __restrict__ bm,
    const float* __restrict__ Wb, const float* __restrict__ bb,
    const float* __restrict__ Wd, const float* __restrict__ rbias_all,
    const float* __restrict__ Wr, const float* __restrict__ br,
    float* __restrict__ RF)
{
    extern __shared__ float smem[];
    float* act = smem;
    uint32_t* BbH = (uint32_t*)(smem + ACT_WORDS);
    uint32_t* BbL = BbH + BPK_WORDS;

    const int tid  = threadIdx.x;
    const int wid  = tid >> 5;
    const int lane = tid & 31;
    const int blk  = blockIdx.x;

    // load enc tile [96][128] into act
    {
        const float* ebase = enc_t + (size_t)blk * 96 * 128;
        for (int i = tid; i < 96 * 32; i += 512) {
            int k = i >> 5, m4 = (i & 31) * 4;
            cp16(act + (size_t)k * ACT_STRIDE + m4, ebase + k * 128 + m4);
        }
        cp_commit(); cp_wait0();
    }
    __syncthreads();

    run_layer<16, true>(act, BbH, BbL, W0, b0, 96, tid, wid, lane);
    for (int l = 0; l < 3; l++)
        run_layer<16, true>(act, BbH, BbL, Wh + l * 65536, bh + l * 256, 256, tid, wid, lane);

    // heads from x1 (= act): sigma (+ mu/sig for coarse)
    float* rf = RF + (size_t)blk * 128 * 6;
    if (wid < 4) {
        int m = wid * 32 + lane;
        float s0 = 0.0f, s1 = 0.0f, s2 = 0.0f;
        for (int k = 0; k < 256; k++) {
            float xv = act[(size_t)k * ACT_STRIDE + m];
            s0 += xv * __ldg(Ws + k);
            if (COARSE) {
                s1 += xv * __ldg(Wm + 2 * k);
                s2 += xv * __ldg(Wm + 2 * k + 1);
            }
        }
        rf[m * 6 + 3] = s0 + __ldg(bs);
        if (COARSE) {
            rf[m * 6 + 4] = s1 + __ldg(bm);
            rf[m * 6 + 5] = s2 + __ldg(bm + 1);
        }
    }
    __syncthreads();

    run_layer<16, false>(act, BbH, BbL, Wb, bb, 256, tid, wid, lane);
    run_layer<8, true>(act, BbH, BbL, Wd, rbias_all + (size_t)blk * 128, 256, tid, wid, lane);

    // rgb head from h (= act rows 0..127)
    if (wid < 4) {
        int m = wid * 32 + lane;
        float r = 0.0f, gg = 0.0f, b = 0.0f;
        for (int k = 0; k < 128; k++) {
            float hv = act[(size_t)k * ACT_STRIDE + m];
            r  += hv * __ldg(Wr + 3 * k);
            gg += hv * __ldg(Wr + 3 * k + 1);
            b  += hv * __ldg(Wr + 3 * k + 2);
        }
        rf[m * 6 + 0] = r  + __ldg(br);
        rf[m * 6 + 1] = gg + __ldg(br + 1);
        rf[m * 6 + 2] = b  + __ldg(br + 2);
    }
}

// ---------------- coarse volume render + PDF ingredients ----------------
__global__ void vrender_coarse_kernel(float* __restrict__ out) {
    int r = blockIdx.x * blockDim.x + threadIdx.x;
    if (r >= NRAYS) return;
    float nrm = g_raynorm[r];
    float T = 1.0f, cr = 0.0f, cg = 0.0f, cb = 0.0f;
    for (int i = 0; i < 128; i++) {
        const float* f = g_rf + (size_t)(r * 128 + i) * 6;
        float t0 = 2.0f + 4.0f * ((float)i / 128.0f);
        float t1 = 2.0f + 4.0f * ((float)(i + 1) / 128.0f);
        float sr = fast_sigmoid(f[0]);
        float sg = fast_sigmoid(f[1]);
        float sb = fast_sigmoid(f[2]);
        float sigma = fmaxf(f[3], 0.0f);
        float alpha = 1.0f - __expf(-sigma * (t1 - t0) * nrm);
        float w = alpha * T;
        T *= (1.0f - alpha + 1e-10f);
        cr += w * sr; cg += w * sg; cb += w * sb;
        int si = r * 128 + i;
        g_weights[si] = w;
        float mu = fast_sigmoid(f[4]);
        float ss = (fast_sigmoid(f[5]) + 0.001f) * 2.0f;
        g_mus[si] = mu;
        g_smsig[si] = ss;
        float l = acdf_((0.0f - mu) / ss);
        g_lt[si] = l;
        g_pib[si] = acdf_((1.0f - mu) / ss) - l;
    }
    out[r * 3 + 0] = cr;
    out[r * 3 + 1] = cg;
    out[r * 3 + 2] = cb;
}

// ---------------- per-ray normalized CDF / PDF ----------------
__global__ void cdf_kernel() {
    int r = blockIdx.x * blockDim.x + threadIdx.x;
    if (r >= NRAYS) return;
    float sum = 0.0f;
    for (int i = 0; i < 128; i++) sum += g_weights[r * 128 + i] + 1e-5f;
    float inv = 1.0f / sum;
    g_cdf[r * 129] = 0.0f;
    float run = 0.0f;
    for (int i = 0; i < 128; i++) {
        float w = (g_weights[r * 128 + i] + 1e-5f) * inv;
        g_pdfn[r * 128 + i] = w;
        run += w;
        g_cdf[r * 129 + i + 1] = run;
    }
}

// ---------------- parallel inverse-CDF fine sampling ----------------
__global__ void fine_sample_kernel() {
    int t = blockIdx.x * blockDim.x + threadIdx.x;
    if (t >= NRAYS * 129) return;
    int r = t / 129;
    int i = t - r * 129;
    const float step = (1.0f - 1e-5f) / 128.0f;
    float u = step * (float)i;
    const float* cdf = g_cdf + r * 129;
    int lo = 0, hi = 128;
    while (lo < hi) {
        int mid = (lo + hi + 1) >> 1;
        if (cdf[mid] <= u) lo = mid; else hi = mid - 1;
    }
    int idx = lo < 127 ? lo : 127;
    float pdfv = g_pdfn[r * 128 + idx];
    float frac = (u - cdf[idx]) / fmaxf(pdfv, 1e-10f);
    frac = fminf(fmaxf(frac, 0.0f), 1.0f);
    int si = r * 128 + idx;
    float p = g_lt[si] + frac * g_pib[si];
    p = fminf(fmaxf(p, 1e-5f), 1.0f - 1e-5f);
    float x = g_mus[si] + g_smsig[si] * 1.4142135623730951f * erfinvf(2.0f * p - 1.0f);
    x = fminf(fmaxf(x, 0.0f), 1.0f);
    float b0 = 2.0f + 4.0f * ((float)idx / 128.0f);
    float b1 = 2.0f + 4.0f * ((float)(idx + 1) / 128.0f);
    g_tfine[r * 129 + i] = b0 + x * (b1 - b0);
}

// ---------------- fine volume render ----------------
__global__ void vrender_fine_kernel(float* __restrict__ out) {
    int r = blockIdx.x * blockDim.x + threadIdx.x;
    if (r >= NRAYS) return;
    float nrm = g_raynorm[r];
    float T = 1.0f, cr = 0.0f, cg = 0.0f, cb = 0.0f, dep = 0.0f, acc = 0.0f;
    for (int i = 0; i < 128; i++) {
        const float* f = g_rf + (size_t)(r * 128 + i) * 6;
        float t0 = g_tfine[r * 129 + i];
        float t1 = g_tfine[r * 129 + i + 1];
        float sr = fast_sigmoid(f[0]);
        float sg = fast_sigmoid(f[1]);
        float sb = fast_sigmoid(f[2]);
        float sigma = fmaxf(f[3], 0.0f);
        float alpha = 1.0f - __expf(-sigma * (t1 - t0) * nrm);
        float w = alpha * T;
        T *= (1.0f - alpha + 1e-10f);
        cr += w * sr; cg += w * sg; cb += w * sb;
        dep += w * 0.5f * (t0 + t1);
        acc += w;
    }
    out[6144 + r * 3 + 0] = cr;
    out[6144 + r * 3 + 1] = cg;
    out[6144 + r * 3 + 2] = cb;
    out[12288 + r] = dep;
    out[14336 + r] = acc;
}

// ---------------- host orchestration ----------------
extern "C" void kernel_launch(void* const* d_in, const int* in_sizes, int n_in,
                              void* d_out, int out_size)
{
    (void)out_size;
    const float* ro = (const float*)d_in[0];
    const float* rd = (const float*)d_in[1];
    const float* rr = (const float*)d_in[2];

    bool sigOrder = (n_in > 15 && in_sizes[15] == 512);
    int fb = sigOrder ? 17 : 15;
    int mb = sigOrder ? 15 : 27;

    const float* cW0 = (const float*)d_in[3];
    const float* cb0 = (const float*)d_in[4];
    const float* cWh = (const float*)d_in[5];
    const float* cbh = (const float*)d_in[6];
    const float* cWs = (const float*)d_in[7];
    const float* cbs = (const float*)d_in[8];
    const float* cWb = (const float*)d_in[9];
    const float* cbb = (const float*)d_in[10];
    const float* cWd = (const float*)d_in[11];
    const float* cbd = (const float*)d_in[12];
    const float* cWr = (const float*)d_in[13];
    const float* cbr = (const float*)d_in[14];
    const float* cWm = (const float*)d_in[mb];
    const float* cbm = (const float*)d_in[mb + 1];
    const float* fW0 = (const float*)d_in[fb + 0];
    const float* fb0 = (const float*)d_in[fb + 1];
    const float* fWh = (const float*)d_in[fb + 2];
    const float* fbh = (const float*)d_in[fb + 3];
    const float* fWs = (const float*)d_in[fb + 4];
    const float* fbs = (const float*)d_in[fb + 5];
    const float* fWb = (const float*)d_in[fb + 6];
    const float* fbb = (const float*)d_in[fb + 7];
    const float* fWd = (const float*)d_in[fb + 8];
    const float* fbd = (const float*)d_in[fb + 9];
    const float* fWr = (const float*)d_in[fb + 10];
    const float* fbr = (const float*)d_in[fb + 11];

    float *p_enc, *p_rf, *p_raybias, *p_tfine;
    cudaGetSymbolAddress((void**)&p_enc, g_enc);
    cudaGetSymbolAddress((void**)&p_rf, g_rf);
    cudaGetSymbolAddress((void**)&p_raybias, g_raybias);
    cudaGetSymbolAddress((void**)&p_tfine, g_tfine);

    cudaFuncSetAttribute(fused_mlp<true>,  cudaFuncAttributeMaxDynamicSharedMemorySize, FUSED_SMEM);
    cudaFuncSetAttribute(fused_mlp<false>, cudaFuncAttributeMaxDynamicSharedMemorySize, FUSED_SMEM);

    float* out = (float*)d_out;

    ray_setup_kernel<<<(NRAYS + 127) / 128, 128>>>(rd);

    // ================= coarse pass =================
    ipe_kernel<<<NS / 128, 128>>>(ro, rd, rr, nullptr);
    ray_bias_kernel<<<NRAYS, 128>>>(cWd, cbd);
    fused_mlp<true><<<NRAYS, 512, FUSED_SMEM>>>(
        p_enc, cW0, cb0, cWh, cbh, cWs, cbs, cWm, cbm,
        cWb, cbb, cWd, p_raybias, cWr, cbr, p_rf);
    vrender_coarse_kernel<<<(NRAYS + 127) / 128, 128>>>(out);
    cdf_kernel<<<(NRAYS + 127) / 128, 128>>>();
    fine_sample_kernel<<<(NRAYS * 129 + 255) / 256, 256>>>();

    // ================= fine pass =================
    ipe_kernel<<<NS / 128, 128>>>(ro, rd, rr, p_tfine);
    ray_bias_kernel<<<NRAYS, 128>>>(fWd, fbd);
    fused_mlp<false><<<NRAYS, 512, FUSED_SMEM>>>(
        p_enc, fW0, fb0, fWh, fbh, fWs, fbs, nullptr, nullptr,
        fWb, fbb, fWd, p_raybias, fWr, fbr, p_rf);
    vrender_fine_kernel<<<(NRAYS + 127) / 128, 128>>>(out);
}